// round 8
// baseline (speedup 1.0000x reference)
#include <cuda_runtime.h>
#include <cuda_bf16.h>
#include <stdint.h>

// ============================================================================
// Problem constants
// ============================================================================
#define P_PAIRS   524288
#define TILE_M    128
#define NTILES    (P_PAIRS / TILE_M)   // 4096
#define THREADS   512

// ---------------- SMEM layout -----------------------------------------------
#define OFF_IDX     0         // 256 int32
#define OFF_W3      1024      // 512 floats
#define OFF_OUT     3072      // 256 floats (partial out accum)
// GEMM1: two 96 KB stages
#define OFF_STAGE   4096
#define STAGE_BYTES 98304
#define ST_AHI      0         // [128 x 64] bf16, 16 KB
#define ST_ALO      16384
#define ST_BHI      32768     // [256 x 64] bf16, 32 KB
#define ST_BLO      65536
// GEMM2 (reuses everything from 4096 after GEMM1):
#define OFF_X1HI    4096      // 4 tiles x [128 x 64] bf16 = 64 KB
#define OFF_X1LO    69632     // 64 KB
#define OFF_B2      135168    // 2 stages x (16 KB hi + 16 KB lo) = 64 KB
#define SMEM_TOTAL  200704

// ============================================================================
// Device scratch: weights pre-split to bf16 hi/lo, transposed to [N][K], and
// pre-swizzled. W1: 8 chunks of [256 x 64] SW128 (32 KB each).
// W2: 8 chunks of [256 x 32] SW64 (16 KB each).
// ============================================================================
__device__ __align__(16) unsigned char g_w1hi[262144];
__device__ __align__(16) unsigned char g_w1lo[262144];
__device__ __align__(16) unsigned char g_w2hi[131072];
__device__ __align__(16) unsigned char g_w2lo[131072];
__device__ int g_idx64;   // 1 if dst/src are int64, 0 if int32

// ============================================================================
// Helpers (plain sm_103-level PTX: ldmatrix / mma.sync / cp.async only)
// ============================================================================
__device__ __forceinline__ uint32_t smem_to_u32(const void* p) {
    uint32_t a;
    asm("{ .reg .u64 t; cvta.to.shared.u64 t, %1; cvt.u32.u64 %0, t; }"
        : "=r"(a) : "l"(p));
    return a;
}

#define SWZ128(o) ((o) ^ (((o) >> 3) & 0x70))
#define SWZ64(o)  ((o) ^ (((o) >> 3) & 0x30))

#define CP16(dst, src) \
    asm volatile("cp.async.cg.shared.global [%0], [%1], 16;" \
        :: "r"(dst), "l"(src))
#define CP_COMMIT() asm volatile("cp.async.commit_group;")
#define CP_WAIT0()  asm volatile("cp.async.wait_group 0;" ::: "memory")
#define CP_WAIT1()  asm volatile("cp.async.wait_group 1;" ::: "memory")

// ldmatrix.x4 from SW128 image with 128-B rows (64 bf16 k-cols)
__device__ __forceinline__ void ldsm4(uint32_t* d, uint32_t base, int r0,
                                      int ks, int lane) {
    int r = r0 + (lane & 15);
    uint32_t byte = (uint32_t)(r * 128 + ks * 32 + (lane >> 4) * 16);
    uint32_t addr = base + SWZ128(byte);
    asm volatile("ldmatrix.sync.aligned.m8n8.x4.shared.b16 {%0,%1,%2,%3}, [%4];"
        : "=r"(d[0]), "=r"(d[1]), "=r"(d[2]), "=r"(d[3]) : "r"(addr));
}

// ldmatrix.x4 from SW64 image with 64-B rows (32 bf16 k-cols)
__device__ __forceinline__ void ldsm4_64(uint32_t* d, uint32_t base, int r0,
                                         int ks16, int lane) {
    int r = r0 + (lane & 15);
    uint32_t byte = (uint32_t)(r * 64 + ks16 * 32 + (lane >> 4) * 16);
    uint32_t addr = base + SWZ64(byte);
    asm volatile("ldmatrix.sync.aligned.m8n8.x4.shared.b16 {%0,%1,%2,%3}, [%4];"
        : "=r"(d[0]), "=r"(d[1]), "=r"(d[2]), "=r"(d[3]) : "r"(addr));
}

__device__ __forceinline__ void mma16816(float* c, const uint32_t* a,
                                         uint32_t b0, uint32_t b1) {
    asm volatile(
        "mma.sync.aligned.m16n8k16.row.col.f32.bf16.bf16.f32 "
        "{%0,%1,%2,%3}, {%4,%5,%6,%7}, {%8,%9}, {%0,%1,%2,%3};"
        : "+f"(c[0]), "+f"(c[1]), "+f"(c[2]), "+f"(c[3])
        : "r"(a[0]), "r"(a[1]), "r"(a[2]), "r"(a[3]), "r"(b0), "r"(b1));
}

__device__ __forceinline__ uint32_t pack_bf2(__nv_bfloat16 a, __nv_bfloat16 b) {
    return (uint32_t)__bfloat16_as_ushort(a) |
           ((uint32_t)__bfloat16_as_ushort(b) << 16);
}

// ============================================================================
// Prologue 1: index dtype detection (parallel). Values < 100000 -> int64
// buffers have all odd 32-bit words zero.
// ============================================================================
__global__ void detect_idx_kernel(const int* __restrict__ p) {
    __shared__ int flag;
    if (threadIdx.x == 0) flag = 1;
    __syncthreads();
    if (p[2 * threadIdx.x + 1] != 0) flag = 0;
    __syncthreads();
    if (threadIdx.x == 0) g_idx64 = flag;
}

// ============================================================================
// Prologue 2: split W1/W2 ([K][N] row-major) into bf16 hi/lo swizzled images.
// ============================================================================
__global__ void prep_weights_kernel(const float* __restrict__ W1,
                                    const float* __restrict__ W2) {
    int t = blockIdx.x * blockDim.x + threadIdx.x;
    if (t < 512 * 256) {
        int k = t >> 8, n = t & 255;
        float f = W1[t];
        __nv_bfloat16 hi = __float2bfloat16_rn(f);
        __nv_bfloat16 lo = __float2bfloat16_rn(f - __bfloat162float(hi));
        uint32_t off = (uint32_t)(n * 128 + (k & 63) * 2);
        uint32_t a = SWZ128(off) + (uint32_t)(k >> 6) * 32768u;
        *(unsigned short*)(g_w1hi + a) = __bfloat16_as_ushort(hi);
        *(unsigned short*)(g_w1lo + a) = __bfloat16_as_ushort(lo);
    } else {
        int t2 = t - 512 * 256;
        if (t2 < 256 * 256) {
            int k = t2 >> 8, n = t2 & 255;
            float f = W2[t2];
            __nv_bfloat16 hi = __float2bfloat16_rn(f);
            __nv_bfloat16 lo = __float2bfloat16_rn(f - __bfloat162float(hi));
            uint32_t off = (uint32_t)(n * 64 + (k & 31) * 2);
            uint32_t a = SWZ64(off) + (uint32_t)(k >> 5) * 16384u;
            *(unsigned short*)(g_w2hi + a) = __bfloat16_as_ushort(hi);
            *(unsigned short*)(g_w2lo + a) = __bfloat16_as_ushort(lo);
        }
    }
}

// ============================================================================
// Main fused kernel. CTA = 128 pairs, 16 warps, warp tile 32(M) x 64(N).
// bf16x3 split GEMMs via mma.sync, software-pipelined fills.
// ============================================================================
__global__ void __launch_bounds__(THREADS, 1)
edge_mlp_kernel(const float* __restrict__ h_nodes,
                const void*  __restrict__ dstp,
                const void*  __restrict__ srcp,
                const float* __restrict__ W3,
                float*       __restrict__ out) {
    extern __shared__ unsigned char smem[];
    uint32_t smem_base = smem_to_u32(smem);
    int tid  = threadIdx.x;
    int lane = tid & 31;
    int wid  = tid >> 5;
    int warp_m = wid & 3;    // 0..3  -> 32 M-rows each
    int warp_n = wid >> 2;   // 0..3  -> 64 N-cols each

    // ---- indices, W3, zero out-accum ----
    int gbase = blockIdx.x * TILE_M;
    int* sm_idx = (int*)(smem + OFF_IDX);
    bool i64 = (g_idx64 != 0);
    if (tid < 128) {
        sm_idx[tid] = i64 ? (int)((const long long*)dstp)[gbase + tid]
                          : ((const int*)dstp)[gbase + tid];
    } else if (tid < 256) {
        int t = tid - 128;
        sm_idx[128 + t] = i64 ? (int)((const long long*)srcp)[gbase + t]
                              : ((const int*)srcp)[gbase + t];
    }
    float* w3s = (float*)(smem + OFF_W3);
    w3s[tid] = W3[tid];
    float* sm_out = (float*)(smem + OFF_OUT);
    if (tid < 256) sm_out[tid] = 0.0f;
    __syncthreads();

    float acc[2][8][4];
    #pragma unroll
    for (int a = 0; a < 2; a++)
        #pragma unroll
        for (int b = 0; b < 8; b++)
            #pragma unroll
            for (int c = 0; c < 4; c++) acc[a][b][c] = 0.0f;

    int m_row = tid >> 2;   // 0..127 (gather row)
    int part  = tid & 3;    // 16 floats each

    // ------------------------------------------------------------------
    // GEMM1: D0[128,256] = concat(h[dst],h[src])[128,512] @ W1
    // Pipelined: A gather prefetched into regs, B via cp.async, 2 stages.
    // ------------------------------------------------------------------
    float4 pref[4];
    {   // prologue: A(0) -> regs, B(0) -> stage 0
        int idx = sm_idx[m_row];
        const float4* rp = (const float4*)(h_nodes + (size_t)idx * 256) + part * 4;
        #pragma unroll
        for (int q = 0; q < 4; q++) pref[q] = rp[q];
        uint32_t dh = smem_base + OFF_STAGE + ST_BHI;
        uint32_t dl = smem_base + OFF_STAGE + ST_BLO;
        #pragma unroll
        for (int i = 0; i < 4; i++) {
            uint32_t o = (uint32_t)(tid * 16 + i * 8192);
            CP16(dh + o, g_w1hi + o);
            CP16(dl + o, g_w1lo + o);
        }
        CP_COMMIT();
    }

    for (int kc = 0; kc < 8; kc++) {
        int s = kc & 1;
        uint32_t stage = OFF_STAGE + (uint32_t)s * STAGE_BYTES;
        // convert + STS A chunk from prefetch regs
        {
            unsigned char* ahi = smem + stage + ST_AHI;
            unsigned char* alo = smem + stage + ST_ALO;
            #pragma unroll
            for (int q = 0; q < 4; q++) {
                float4 v = pref[q];
                int j0 = part * 16 + q * 4;
                uint32_t sw = SWZ128((uint32_t)(m_row * 128 + j0 * 2));
                __nv_bfloat16 h0 = __float2bfloat16_rn(v.x);
                __nv_bfloat16 h1 = __float2bfloat16_rn(v.y);
                __nv_bfloat16 h2 = __float2bfloat16_rn(v.z);
                __nv_bfloat16 h3 = __float2bfloat16_rn(v.w);
                *(uint32_t*)(ahi + sw)     = pack_bf2(h0, h1);
                *(uint32_t*)(ahi + sw + 4) = pack_bf2(h2, h3);
                __nv_bfloat16 l0 = __float2bfloat16_rn(v.x - __bfloat162float(h0));
                __nv_bfloat16 l1 = __float2bfloat16_rn(v.y - __bfloat162float(h1));
                __nv_bfloat16 l2 = __float2bfloat16_rn(v.z - __bfloat162float(h2));
                __nv_bfloat16 l3 = __float2bfloat16_rn(v.w - __bfloat162float(h3));
                *(uint32_t*)(alo + sw)     = pack_bf2(l0, l1);
                *(uint32_t*)(alo + sw + 4) = pack_bf2(l2, l3);
            }
        }
        // prefetch next chunk (A regs + B cp.async into other stage)
        if (kc < 7) {
            int kn = kc + 1;
            int idx = sm_idx[((kn < 4) ? 0 : 128) + m_row];
            const float4* rp = (const float4*)(h_nodes + (size_t)idx * 256 +
                                               (kn & 3) * 64) + part * 4;
            #pragma unroll
            for (int q = 0; q < 4; q++) pref[q] = rp[q];
            uint32_t nstage = OFF_STAGE + (uint32_t)(s ^ 1) * STAGE_BYTES;
            uint32_t dh = smem_base + nstage + ST_BHI;
            uint32_t dl = smem_base + nstage + ST_BLO;
            const unsigned char* gh = g_w1hi + kn * 32768;
            const unsigned char* gl = g_w1lo + kn * 32768;
            #pragma unroll
            for (int i = 0; i < 4; i++) {
                uint32_t o = (uint32_t)(tid * 16 + i * 8192);
                CP16(dh + o, gh + o);
                CP16(dl + o, gl + o);
            }
            CP_COMMIT();
            CP_WAIT1();    // current chunk's B group done
        } else {
            CP_WAIT0();
        }
        __syncthreads();
        // compute 64-k chunk (term-major: dependent-MMA distance = 4)
        uint32_t aHiB = smem_base + stage + ST_AHI;
        uint32_t aLoB = smem_base + stage + ST_ALO;
        uint32_t bHiB = smem_base + stage + ST_BHI;
        uint32_t bLoB = smem_base + stage + ST_BLO;
        #pragma unroll
        for (int ks = 0; ks < 4; ks++) {
            uint32_t ah[2][4], al[2][4];
            ldsm4(ah[0], aHiB, warp_m * 32,      ks, lane);
            ldsm4(ah[1], aHiB, warp_m * 32 + 16, ks, lane);
            ldsm4(al[0], aLoB, warp_m * 32,      ks, lane);
            ldsm4(al[1], aLoB, warp_m * 32 + 16, ks, lane);
            #pragma unroll
            for (int ng = 0; ng < 4; ng++) {
                uint32_t bh[4], bl[4];
                ldsm4(bh, bHiB, warp_n * 64 + ng * 16, ks, lane);
                ldsm4(bl, bLoB, warp_n * 64 + ng * 16, ks, lane);
                // hh
                mma16816(acc[0][ng * 2 + 0], ah[0], bh[0], bh[2]);
                mma16816(acc[0][ng * 2 + 1], ah[0], bh[1], bh[3]);
                mma16816(acc[1][ng * 2 + 0], ah[1], bh[0], bh[2]);
                mma16816(acc[1][ng * 2 + 1], ah[1], bh[1], bh[3]);
                // hl
                mma16816(acc[0][ng * 2 + 0], ah[0], bl[0], bl[2]);
                mma16816(acc[0][ng * 2 + 1], ah[0], bl[1], bl[3]);
                mma16816(acc[1][ng * 2 + 0], ah[1], bl[0], bl[2]);
                mma16816(acc[1][ng * 2 + 1], ah[1], bl[1], bl[3]);
                // lh
                mma16816(acc[0][ng * 2 + 0], al[0], bh[0], bh[2]);
                mma16816(acc[0][ng * 2 + 1], al[0], bh[1], bh[3]);
                mma16816(acc[1][ng * 2 + 0], al[1], bh[0], bh[2]);
                mma16816(acc[1][ng * 2 + 1], al[1], bh[1], bh[3]);
            }
        }
        __syncthreads();
    }

    // Prefetch GEMM2 B chunk 0 (overlaps epilogue 1). Target region was
    // GEMM1 stage-1 B, whose last reader (compute kc=7) has synced above.
    {
        uint32_t dh = smem_base + OFF_B2;
        #pragma unroll
        for (int i = 0; i < 2; i++) {
            uint32_t o = (uint32_t)(tid * 16 + i * 8192);
            CP16(dh + o,         g_w2hi + o);
            CP16(dh + 16384 + o, g_w2lo + o);
        }
        CP_COMMIT();
    }

    // ------------------------------------------------------------------
    // Epilogue 1: ReLU + bf16 hi/lo split -> X1 (4 SW128 tiles)
    // ------------------------------------------------------------------
    {
        unsigned char* x1h = smem + OFF_X1HI + warp_n * 16384;
        unsigned char* x1l = smem + OFF_X1LO + warp_n * 16384;
        int r0 = warp_m * 32 + (lane >> 2);
        int qb = 2 * (lane & 3);
        #pragma unroll
        for (int mf = 0; mf < 2; mf++) {
            #pragma unroll
            for (int nf = 0; nf < 8; nf++) {
                int qq = nf * 8 + qb;
                #pragma unroll
                for (int half = 0; half < 2; half++) {
                    float v0 = acc[mf][nf][half * 2 + 0];
                    float v1 = acc[mf][nf][half * 2 + 1];
                    v0 = v0 > 0.f ? v0 : 0.f;
                    v1 = v1 > 0.f ? v1 : 0.f;
                    __nv_bfloat16 h0 = __float2bfloat16_rn(v0);
                    __nv_bfloat16 h1 = __float2bfloat16_rn(v1);
                    __nv_bfloat16 l0 = __float2bfloat16_rn(v0 - __bfloat162float(h0));
                    __nv_bfloat16 l1 = __float2bfloat16_rn(v1 - __bfloat162float(h1));
                    int row = r0 + mf * 16 + half * 8;
                    uint32_t sw = SWZ128((uint32_t)(row * 128 + qq * 2));
                    *(uint32_t*)(x1h + sw) = pack_bf2(h0, h1);
                    *(uint32_t*)(x1l + sw) = pack_bf2(l0, l1);
                }
            }
        }
    }

    // re-zero accumulators for GEMM2
    #pragma unroll
    for (int a = 0; a < 2; a++)
        #pragma unroll
        for (int b = 0; b < 8; b++)
            #pragma unroll
            for (int c = 0; c < 4; c++) acc[a][b][c] = 0.0f;

    // ------------------------------------------------------------------
    // GEMM2: D1[128,256] = X1[128,256] @ W2. 8 chunks of k=32 (SW64 B),
    // double-buffered cp.async pipeline.
    // ------------------------------------------------------------------
    for (int kc = 0; kc < 8; kc++) {
        int s = kc & 1;
        if (kc < 7) {
            int kn = kc + 1;
            uint32_t dh = smem_base + OFF_B2 + (uint32_t)(s ^ 1) * 32768u;
            const unsigned char* gh = g_w2hi + kn * 16384;
            const unsigned char* gl = g_w2lo + kn * 16384;
            #pragma unroll
            for (int i = 0; i < 2; i++) {
                uint32_t o = (uint32_t)(tid * 16 + i * 8192);
                CP16(dh + o,         gh + o);
                CP16(dh + 16384 + o, gl + o);
            }
            CP_COMMIT();
            CP_WAIT1();
        } else {
            CP_WAIT0();
        }
        __syncthreads();   // publishes X1 (kc==0) and current B2 stage
        int tile = kc >> 1;
        uint32_t aHiB = smem_base + OFF_X1HI + (uint32_t)tile * 16384u;
        uint32_t aLoB = smem_base + OFF_X1LO + (uint32_t)tile * 16384u;
        uint32_t bHiB = smem_base + OFF_B2 + (uint32_t)s * 32768u;
        uint32_t bLoB = bHiB + 16384u;
        #pragma unroll
        for (int ks16 = 0; ks16 < 2; ks16++) {
            int kwin = (kc & 1) * 2 + ks16;   // 16-col slot within SW128 tile
            uint32_t ah[2][4], al[2][4];
            ldsm4(ah[0], aHiB, warp_m * 32,      kwin, lane);
            ldsm4(ah[1], aHiB, warp_m * 32 + 16, kwin, lane);
            ldsm4(al[0], aLoB, warp_m * 32,      kwin, lane);
            ldsm4(al[1], aLoB, warp_m * 32 + 16, kwin, lane);
            #pragma unroll
            for (int ng = 0; ng < 4; ng++) {
                uint32_t bh[4], bl[4];
                ldsm4_64(bh, bHiB, warp_n * 64 + ng * 16, ks16, lane);
                ldsm4_64(bl, bLoB, warp_n * 64 + ng * 16, ks16, lane);
                mma16816(acc[0][ng * 2 + 0], ah[0], bh[0], bh[2]);
                mma16816(acc[0][ng * 2 + 1], ah[0], bh[1], bh[3]);
                mma16816(acc[1][ng * 2 + 0], ah[1], bh[0], bh[2]);
                mma16816(acc[1][ng * 2 + 1], ah[1], bh[1], bh[3]);
                mma16816(acc[0][ng * 2 + 0], ah[0], bl[0], bl[2]);
                mma16816(acc[0][ng * 2 + 1], ah[0], bl[1], bl[3]);
                mma16816(acc[1][ng * 2 + 0], ah[1], bl[0], bl[2]);
                mma16816(acc[1][ng * 2 + 1], ah[1], bl[1], bl[3]);
                mma16816(acc[0][ng * 2 + 0], al[0], bh[0], bh[2]);
                mma16816(acc[0][ng * 2 + 1], al[0], bh[1], bh[3]);
                mma16816(acc[1][ng * 2 + 0], al[1], bh[0], bh[2]);
                mma16816(acc[1][ng * 2 + 1], al[1], bh[1], bh[3]);
            }
        }
        __syncthreads();
    }

    // ------------------------------------------------------------------
    // Epilogue 2 (fused GEMM3): out[m,:] = ReLU(D1[m,:]) @ W3[256,2]
    // ------------------------------------------------------------------
    {
        float p[4][2];
        #pragma unroll
        for (int r = 0; r < 4; r++) { p[r][0] = 0.f; p[r][1] = 0.f; }
        int qb = 2 * (lane & 3);
        #pragma unroll
        for (int mf = 0; mf < 2; mf++) {
            #pragma unroll
            for (int nf = 0; nf < 8; nf++) {
                #pragma unroll
                for (int i = 0; i < 4; i++) {
                    float v = acc[mf][nf][i];
                    v = v > 0.f ? v : 0.f;
                    int rsel = mf * 2 + (i >> 1);
                    int n = warp_n * 64 + nf * 8 + qb + (i & 1);
                    p[rsel][0] = fmaf(v, w3s[2 * n],     p[rsel][0]);
                    p[rsel][1] = fmaf(v, w3s[2 * n + 1], p[rsel][1]);
                }
            }
        }
        #pragma unroll
        for (int r = 0; r < 4; r++) {
            #pragma unroll
            for (int c = 0; c < 2; c++) {
                p[r][c] += __shfl_xor_sync(0xffffffffu, p[r][c], 1);
                p[r][c] += __shfl_xor_sync(0xffffffffu, p[r][c], 2);
            }
        }
        if ((lane & 3) == 0) {
            #pragma unroll
            for (int r = 0; r < 4; r++) {
                int row = warp_m * 32 + (r >> 1) * 16 + (r & 1) * 8 + (lane >> 2);
                atomicAdd(&sm_out[row * 2 + 0], p[r][0]);
                atomicAdd(&sm_out[row * 2 + 1], p[r][1]);
            }
        }
    }
    __syncthreads();
    if (tid < 256)
        out[(size_t)gbase * 2 + tid] = sm_out[tid];
}

// ============================================================================
// Launch
// ============================================================================
extern "C" void kernel_launch(void* const* d_in, const int* in_sizes, int n_in,
                              void* d_out, int out_size) {
    const float* h_nodes = (const float*)d_in[0];
    const void*  dstp    = d_in[1];
    const void*  srcp    = d_in[2];
    const float* W1      = (const float*)d_in[3];
    const float* W2      = (const float*)d_in[4];
    const float* W3      = (const float*)d_in[5];
    float*       out     = (float*)d_out;

    detect_idx_kernel<<<1, 128>>>((const int*)dstp);
    prep_weights_kernel<<<768, 256>>>(W1, W2);

    cudaFuncSetAttribute(edge_mlp_kernel,
                         cudaFuncAttributeMaxDynamicSharedMemorySize, SMEM_TOTAL);
    edge_mlp_kernel<<<NTILES, THREADS, SMEM_TOTAL>>>(h_nodes, dstp, srcp, W3, out);
}

// round 9
// speedup vs baseline: 1.0199x; 1.0199x over previous
#include <cuda_runtime.h>
#include <cuda_fp16.h>
#include <stdint.h>

// ============================================================================
// Problem constants
// ============================================================================
#define P_PAIRS   524288
#define TILE_M    128
#define NTILES    (P_PAIRS / TILE_M)   // 4096
#define THREADS   512

// ---------------- SMEM layout -----------------------------------------------
#define OFF_IDX     0         // 256 int32
#define OFF_W3      1024      // 512 floats
#define OFF_OUT     3072      // 256 floats (partial out accum)
// GEMM1: two 80 KB stages
#define OFF_STAGE   4096
#define STAGE_BYTES 81920
#define ST_A        0         // [128 x 64] fp16, 16 KB (single precision term)
#define ST_BHI      16384     // [256 x 64] fp16, 32 KB
#define ST_BLO      49152     // 32 KB
// GEMM2 (reuses region from 4096 after GEMM1):
#define OFF_X1      4096      // 4 tiles x [128 x 64] fp16 = 64 KB
#define OFF_B2      69632     // 2 stages x (16 KB hi + 16 KB lo) = 64 KB
#define SMEM_TOTAL  167936

// ============================================================================
// Device scratch: weights pre-split to fp16 hi/lo, transposed to [N][K], and
// pre-swizzled. W1: 8 chunks of [256 x 64] SW128 (32 KB each).
// W2: 8 chunks of [256 x 32] SW64 (16 KB each).
// ============================================================================
__device__ __align__(16) unsigned char g_w1hi[262144];
__device__ __align__(16) unsigned char g_w1lo[262144];
__device__ __align__(16) unsigned char g_w2hi[131072];
__device__ __align__(16) unsigned char g_w2lo[131072];
__device__ int g_idx64;   // 1 if dst/src are int64, 0 if int32

// ============================================================================
// Helpers (plain sm_103-level PTX: ldmatrix / mma.sync / cp.async only)
// ============================================================================
__device__ __forceinline__ uint32_t smem_to_u32(const void* p) {
    uint32_t a;
    asm("{ .reg .u64 t; cvta.to.shared.u64 t, %1; cvt.u32.u64 %0, t; }"
        : "=r"(a) : "l"(p));
    return a;
}

#define SWZ128(o) ((o) ^ (((o) >> 3) & 0x70))
#define SWZ64(o)  ((o) ^ (((o) >> 3) & 0x30))

#define CP16(dst, src) \
    asm volatile("cp.async.cg.shared.global [%0], [%1], 16;" \
        :: "r"(dst), "l"(src))
#define CP_COMMIT() asm volatile("cp.async.commit_group;")
#define CP_WAIT0()  asm volatile("cp.async.wait_group 0;" ::: "memory")
#define CP_WAIT1()  asm volatile("cp.async.wait_group 1;" ::: "memory")

// ldmatrix.x4 from SW128 image with 128-B rows (64 fp16 k-cols)
__device__ __forceinline__ void ldsm4(uint32_t* d, uint32_t base, int r0,
                                      int ks, int lane) {
    int r = r0 + (lane & 15);
    uint32_t byte = (uint32_t)(r * 128 + ks * 32 + (lane >> 4) * 16);
    uint32_t addr = base + SWZ128(byte);
    asm volatile("ldmatrix.sync.aligned.m8n8.x4.shared.b16 {%0,%1,%2,%3}, [%4];"
        : "=r"(d[0]), "=r"(d[1]), "=r"(d[2]), "=r"(d[3]) : "r"(addr));
}

// ldmatrix.x4 from SW64 image with 64-B rows (32 fp16 k-cols)
__device__ __forceinline__ void ldsm4_64(uint32_t* d, uint32_t base, int r0,
                                         int ks16, int lane) {
    int r = r0 + (lane & 15);
    uint32_t byte = (uint32_t)(r * 64 + ks16 * 32 + (lane >> 4) * 16);
    uint32_t addr = base + SWZ64(byte);
    asm volatile("ldmatrix.sync.aligned.m8n8.x4.shared.b16 {%0,%1,%2,%3}, [%4];"
        : "=r"(d[0]), "=r"(d[1]), "=r"(d[2]), "=r"(d[3]) : "r"(addr));
}

__device__ __forceinline__ void mma16816(float* c, const uint32_t* a,
                                         uint32_t b0, uint32_t b1) {
    asm volatile(
        "mma.sync.aligned.m16n8k16.row.col.f32.f16.f16.f32 "
        "{%0,%1,%2,%3}, {%4,%5,%6,%7}, {%8,%9}, {%0,%1,%2,%3};"
        : "+f"(c[0]), "+f"(c[1]), "+f"(c[2]), "+f"(c[3])
        : "r"(a[0]), "r"(a[1]), "r"(a[2]), "r"(a[3]), "r"(b0), "r"(b1));
}

__device__ __forceinline__ uint32_t pack_h2(float a, float b) {
    __half2 h = __floats2half2_rn(a, b);   // a -> low half (k even)
    return *reinterpret_cast<uint32_t*>(&h);
}

// ============================================================================
// Prologue 1: index dtype detection (parallel). Values < 100000 -> int64
// buffers have all odd 32-bit words zero.
// ============================================================================
__global__ void detect_idx_kernel(const int* __restrict__ p) {
    __shared__ int flag;
    if (threadIdx.x == 0) flag = 1;
    __syncthreads();
    if (p[2 * threadIdx.x + 1] != 0) flag = 0;
    __syncthreads();
    if (threadIdx.x == 0) g_idx64 = flag;
}

// ============================================================================
// Prologue 2: split W1/W2 ([K][N] row-major) into fp16 hi/lo swizzled images.
// hi = rn(f); lo = rn(f - hi) (lo is subnormal-small; only ~2 bits needed).
// ============================================================================
__global__ void prep_weights_kernel(const float* __restrict__ W1,
                                    const float* __restrict__ W2) {
    int t = blockIdx.x * blockDim.x + threadIdx.x;
    if (t < 512 * 256) {
        int k = t >> 8, n = t & 255;
        float f = W1[t];
        __half hi = __float2half_rn(f);
        __half lo = __float2half_rn(f - __half2float(hi));
        uint32_t off = (uint32_t)(n * 128 + (k & 63) * 2);
        uint32_t a = SWZ128(off) + (uint32_t)(k >> 6) * 32768u;
        *(unsigned short*)(g_w1hi + a) = *(unsigned short*)&hi;
        *(unsigned short*)(g_w1lo + a) = *(unsigned short*)&lo;
    } else {
        int t2 = t - 512 * 256;
        if (t2 < 256 * 256) {
            int k = t2 >> 8, n = t2 & 255;
            float f = W2[t2];
            __half hi = __float2half_rn(f);
            __half lo = __float2half_rn(f - __half2float(hi));
            uint32_t off = (uint32_t)(n * 64 + (k & 31) * 2);
            uint32_t a = SWZ64(off) + (uint32_t)(k >> 5) * 16384u;
            *(unsigned short*)(g_w2hi + a) = *(unsigned short*)&hi;
            *(unsigned short*)(g_w2lo + a) = *(unsigned short*)&lo;
        }
    }
}

// ============================================================================
// Main fused kernel. CTA = 128 pairs, 16 warps, warp tile 32(M) x 64(N).
// fp16x2 split GEMMs (A fp16, B = hi + lo) via mma.sync, pipelined fills.
// ============================================================================
__global__ void __launch_bounds__(THREADS, 1)
edge_mlp_kernel(const float* __restrict__ h_nodes,
                const void*  __restrict__ dstp,
                const void*  __restrict__ srcp,
                const float* __restrict__ W3,
                float*       __restrict__ out) {
    extern __shared__ unsigned char smem[];
    uint32_t smem_base = smem_to_u32(smem);
    int tid  = threadIdx.x;
    int lane = tid & 31;
    int wid  = tid >> 5;
    int warp_m = wid & 3;    // 0..3  -> 32 M-rows each
    int warp_n = wid >> 2;   // 0..3  -> 64 N-cols each

    // ---- indices, W3, zero out-accum ----
    int gbase = blockIdx.x * TILE_M;
    int* sm_idx = (int*)(smem + OFF_IDX);
    bool i64 = (g_idx64 != 0);
    if (tid < 128) {
        sm_idx[tid] = i64 ? (int)((const long long*)dstp)[gbase + tid]
                          : ((const int*)dstp)[gbase + tid];
    } else if (tid < 256) {
        int t = tid - 128;
        sm_idx[128 + t] = i64 ? (int)((const long long*)srcp)[gbase + t]
                              : ((const int*)srcp)[gbase + t];
    }
    float* w3s = (float*)(smem + OFF_W3);
    w3s[tid] = W3[tid];
    float* sm_out = (float*)(smem + OFF_OUT);
    if (tid < 256) sm_out[tid] = 0.0f;
    __syncthreads();

    float acc[2][8][4];
    #pragma unroll
    for (int a = 0; a < 2; a++)
        #pragma unroll
        for (int b = 0; b < 8; b++)
            #pragma unroll
            for (int c = 0; c < 4; c++) acc[a][b][c] = 0.0f;

    int m_row = tid >> 2;   // 0..127 (gather row)
    int part  = tid & 3;    // 16 floats each

    // ------------------------------------------------------------------
    // GEMM1: D0[128,256] = concat(h[dst],h[src])[128,512] @ W1
    // Pipelined: A gather prefetched to regs, B via cp.async, 2 stages.
    // ------------------------------------------------------------------
    float4 pref[4];
    {   // prologue: A(0) -> regs, B(0) -> stage 0
        int idx = sm_idx[m_row];
        const float4* rp = (const float4*)(h_nodes + (size_t)idx * 256) + part * 4;
        #pragma unroll
        for (int q = 0; q < 4; q++) pref[q] = rp[q];
        uint32_t dh = smem_base + OFF_STAGE + ST_BHI;
        uint32_t dl = smem_base + OFF_STAGE + ST_BLO;
        #pragma unroll
        for (int i = 0; i < 4; i++) {
            uint32_t o = (uint32_t)(tid * 16 + i * 8192);
            CP16(dh + o, g_w1hi + o);
            CP16(dl + o, g_w1lo + o);
        }
        CP_COMMIT();
    }

    for (int kc = 0; kc < 8; kc++) {
        int s = kc & 1;
        uint32_t stage = OFF_STAGE + (uint32_t)s * STAGE_BYTES;
        // convert + STS A chunk from prefetch regs (fp16, single term)
        {
            unsigned char* ap = smem + stage + ST_A;
            #pragma unroll
            for (int qq = 0; qq < 2; qq++) {
                float4 v0 = pref[2 * qq];
                float4 v1 = pref[2 * qq + 1];
                int j0 = part * 16 + qq * 8;
                uint32_t sw = SWZ128((uint32_t)(m_row * 128 + j0 * 2));
                uint4 st;
                st.x = pack_h2(v0.x, v0.y);
                st.y = pack_h2(v0.z, v0.w);
                st.z = pack_h2(v1.x, v1.y);
                st.w = pack_h2(v1.z, v1.w);
                *(uint4*)(ap + sw) = st;
            }
        }
        // prefetch next chunk (A regs + B cp.async into other stage)
        if (kc < 7) {
            int kn = kc + 1;
            int idx = sm_idx[((kn < 4) ? 0 : 128) + m_row];
            const float4* rp = (const float4*)(h_nodes + (size_t)idx * 256 +
                                               (kn & 3) * 64) + part * 4;
            #pragma unroll
            for (int q = 0; q < 4; q++) pref[q] = rp[q];
            uint32_t nstage = OFF_STAGE + (uint32_t)(s ^ 1) * STAGE_BYTES;
            uint32_t dh = smem_base + nstage + ST_BHI;
            uint32_t dl = smem_base + nstage + ST_BLO;
            const unsigned char* gh = g_w1hi + kn * 32768;
            const unsigned char* gl = g_w1lo + kn * 32768;
            #pragma unroll
            for (int i = 0; i < 4; i++) {
                uint32_t o = (uint32_t)(tid * 16 + i * 8192);
                CP16(dh + o, gh + o);
                CP16(dl + o, gl + o);
            }
            CP_COMMIT();
            CP_WAIT1();    // current chunk's B group done
        } else {
            CP_WAIT0();
        }
        __syncthreads();
        // compute 64-k chunk: 2 terms (A.Bhi + A.Blo), dep distance 4
        uint32_t aB   = smem_base + stage + ST_A;
        uint32_t bHiB = smem_base + stage + ST_BHI;
        uint32_t bLoB = smem_base + stage + ST_BLO;
        #pragma unroll
        for (int ks = 0; ks < 4; ks++) {
            uint32_t ah[2][4];
            ldsm4(ah[0], aB, warp_m * 32,      ks, lane);
            ldsm4(ah[1], aB, warp_m * 32 + 16, ks, lane);
            #pragma unroll
            for (int ng = 0; ng < 4; ng++) {
                uint32_t bh[4], bl[4];
                ldsm4(bh, bHiB, warp_n * 64 + ng * 16, ks, lane);
                ldsm4(bl, bLoB, warp_n * 64 + ng * 16, ks, lane);
                // term hi
                mma16816(acc[0][ng * 2 + 0], ah[0], bh[0], bh[2]);
                mma16816(acc[0][ng * 2 + 1], ah[0], bh[1], bh[3]);
                mma16816(acc[1][ng * 2 + 0], ah[1], bh[0], bh[2]);
                mma16816(acc[1][ng * 2 + 1], ah[1], bh[1], bh[3]);
                // term lo
                mma16816(acc[0][ng * 2 + 0], ah[0], bl[0], bl[2]);
                mma16816(acc[0][ng * 2 + 1], ah[0], bl[1], bl[3]);
                mma16816(acc[1][ng * 2 + 0], ah[1], bl[0], bl[2]);
                mma16816(acc[1][ng * 2 + 1], ah[1], bl[1], bl[3]);
            }
        }
        __syncthreads();
    }

    // Prefetch GEMM2 B chunk 0 (overlaps epilogue 1). Region was GEMM1
    // stage space; last readers synced above.
    {
        uint32_t dh = smem_base + OFF_B2;
        #pragma unroll
        for (int i = 0; i < 1; i++) {
            uint32_t o = (uint32_t)(tid * 16);
            CP16(dh + o,          g_w2hi + o);
            CP16(dh + o + 8192,   g_w2hi + o + 8192);
            CP16(dh + 16384 + o,        g_w2lo + o);
            CP16(dh + 16384 + o + 8192, g_w2lo + o + 8192);
        }
        CP_COMMIT();
    }

    // ------------------------------------------------------------------
    // Epilogue 1: ReLU + fp16 convert -> X1 (4 SW128 tiles, single image)
    // ------------------------------------------------------------------
    {
        unsigned char* x1 = smem + OFF_X1 + warp_n * 16384;
        int r0 = warp_m * 32 + (lane >> 2);
        int qb = 2 * (lane & 3);
        #pragma unroll
        for (int mf = 0; mf < 2; mf++) {
            #pragma unroll
            for (int nf = 0; nf < 8; nf++) {
                int qq = nf * 8 + qb;
                #pragma unroll
                for (int half = 0; half < 2; half++) {
                    float v0 = acc[mf][nf][half * 2 + 0];
                    float v1 = acc[mf][nf][half * 2 + 1];
                    v0 = v0 > 0.f ? v0 : 0.f;
                    v1 = v1 > 0.f ? v1 : 0.f;
                    int row = r0 + mf * 16 + half * 8;
                    uint32_t sw = SWZ128((uint32_t)(row * 128 + qq * 2));
                    *(uint32_t*)(x1 + sw) = pack_h2(v0, v1);
                }
            }
        }
    }

    // re-zero accumulators for GEMM2
    #pragma unroll
    for (int a = 0; a < 2; a++)
        #pragma unroll
        for (int b = 0; b < 8; b++)
            #pragma unroll
            for (int c = 0; c < 4; c++) acc[a][b][c] = 0.0f;

    // ------------------------------------------------------------------
    // GEMM2: D1[128,256] = X1[128,256] @ W2. 8 chunks of k=32 (SW64 B),
    // double-buffered cp.async pipeline.
    // ------------------------------------------------------------------
    for (int kc = 0; kc < 8; kc++) {
        int s = kc & 1;
        if (kc < 7) {
            int kn = kc + 1;
            uint32_t dh = smem_base + OFF_B2 + (uint32_t)(s ^ 1) * 32768u;
            const unsigned char* gh = g_w2hi + kn * 16384;
            const unsigned char* gl = g_w2lo + kn * 16384;
            #pragma unroll
            for (int i = 0; i < 2; i++) {
                uint32_t o = (uint32_t)(tid * 16 + i * 8192);
                CP16(dh + o,         gh + o);
                CP16(dh + 16384 + o, gl + o);
            }
            CP_COMMIT();
            CP_WAIT1();
        } else {
            CP_WAIT0();
        }
        __syncthreads();   // publishes X1 (kc==0) and current B2 stage
        int tile = kc >> 1;
        uint32_t aB   = smem_base + OFF_X1 + (uint32_t)tile * 16384u;
        uint32_t bHiB = smem_base + OFF_B2 + (uint32_t)s * 32768u;
        uint32_t bLoB = bHiB + 16384u;
        #pragma unroll
        for (int ks16 = 0; ks16 < 2; ks16++) {
            int kwin = (kc & 1) * 2 + ks16;   // 16-col slot within SW128 tile
            uint32_t ah[2][4];
            ldsm4(ah[0], aB, warp_m * 32,      kwin, lane);
            ldsm4(ah[1], aB, warp_m * 32 + 16, kwin, lane);
            #pragma unroll
            for (int ng = 0; ng < 4; ng++) {
                uint32_t bh[4], bl[4];
                ldsm4_64(bh, bHiB, warp_n * 64 + ng * 16, ks16, lane);
                ldsm4_64(bl, bLoB, warp_n * 64 + ng * 16, ks16, lane);
                mma16816(acc[0][ng * 2 + 0], ah[0], bh[0], bh[2]);
                mma16816(acc[0][ng * 2 + 1], ah[0], bh[1], bh[3]);
                mma16816(acc[1][ng * 2 + 0], ah[1], bh[0], bh[2]);
                mma16816(acc[1][ng * 2 + 1], ah[1], bh[1], bh[3]);
                mma16816(acc[0][ng * 2 + 0], ah[0], bl[0], bl[2]);
                mma16816(acc[0][ng * 2 + 1], ah[0], bl[1], bl[3]);
                mma16816(acc[1][ng * 2 + 0], ah[1], bl[0], bl[2]);
                mma16816(acc[1][ng * 2 + 1], ah[1], bl[1], bl[3]);
            }
        }
        __syncthreads();
    }

    // ------------------------------------------------------------------
    // Epilogue 2 (fused GEMM3): out[m,:] = ReLU(D1[m,:]) @ W3[256,2]
    // ------------------------------------------------------------------
    {
        float p[4][2];
        #pragma unroll
        for (int r = 0; r < 4; r++) { p[r][0] = 0.f; p[r][1] = 0.f; }
        int qb = 2 * (lane & 3);
        #pragma unroll
        for (int mf = 0; mf < 2; mf++) {
            #pragma unroll
            for (int nf = 0; nf < 8; nf++) {
                #pragma unroll
                for (int i = 0; i < 4; i++) {
                    float v = acc[mf][nf][i];
                    v = v > 0.f ? v : 0.f;
                    int rsel = mf * 2 + (i >> 1);
                    int n = warp_n * 64 + nf * 8 + qb + (i & 1);
                    p[rsel][0] = fmaf(v, w3s[2 * n],     p[rsel][0]);
                    p[rsel][1] = fmaf(v, w3s[2 * n + 1], p[rsel][1]);
                }
            }
        }
        #pragma unroll
        for (int r = 0; r < 4; r++) {
            #pragma unroll
            for (int c = 0; c < 2; c++) {
                p[r][c] += __shfl_xor_sync(0xffffffffu, p[r][c], 1);
                p[r][c] += __shfl_xor_sync(0xffffffffu, p[r][c], 2);
            }
        }
        if ((lane & 3) == 0) {
            #pragma unroll
            for (int r = 0; r < 4; r++) {
                int row = warp_m * 32 + (r >> 1) * 16 + (r & 1) * 8 + (lane >> 2);
                atomicAdd(&sm_out[row * 2 + 0], p[r][0]);
                atomicAdd(&sm_out[row * 2 + 1], p[r][1]);
            }
        }
    }
    __syncthreads();
    if (tid < 256)
        out[(size_t)gbase * 2 + tid] = sm_out[tid];
}

// ============================================================================
// Launch
// ============================================================================
extern "C" void kernel_launch(void* const* d_in, const int* in_sizes, int n_in,
                              void* d_out, int out_size) {
    const float* h_nodes = (const float*)d_in[0];
    const void*  dstp    = d_in[1];
    const void*  srcp    = d_in[2];
    const float* W1      = (const float*)d_in[3];
    const float* W2      = (const float*)d_in[4];
    const float* W3      = (const float*)d_in[5];
    float*       out     = (float*)d_out;

    detect_idx_kernel<<<1, 128>>>((const int*)dstp);
    prep_weights_kernel<<<768, 256>>>(W1, W2);

    cudaFuncSetAttribute(edge_mlp_kernel,
                         cudaFuncAttributeMaxDynamicSharedMemorySize, SMEM_TOTAL);
    edge_mlp_kernel<<<NTILES, THREADS, SMEM_TOTAL>>>(h_nodes, dstp, srcp, W3, out);
}

// round 10
// speedup vs baseline: 2.6833x; 2.6309x over previous
#include <cuda_runtime.h>
#include <cuda_fp16.h>
#include <stdint.h>

// ============================================================================
// Problem constants
// ============================================================================
#define P_PAIRS   524288
#define TILE_M    64
#define NTILES    (P_PAIRS / TILE_M)   // 8192
#define THREADS   256

// ---------------- SMEM layout (84 KB -> 2 CTAs/SM) ---------------------------
#define OFF_IDX     0         // 128 int32
#define OFF_W3      1024      // 512 floats
#define OFF_OUT     3072      // 128 floats (partial out accum)
// GEMM1: two 40 KB stages
#define OFF_STAGE   4096
#define STAGE_BYTES 40960
#define ST_A        0         // [64 x 64] fp16, 8 KB
#define ST_B        8192      // [256 x 64] fp16, 32 KB
// GEMM2 (reuses stage region after GEMM1):
#define OFF_X1      4096      // 4 tiles x [64 x 64] fp16 = 32 KB
#define OFF_B2      36864     // 2 stages x 16 KB = 32 KB
#define SMEM_TOTAL  86016

// ============================================================================
// Device scratch: weights as plain fp16, transposed to [N][K], pre-swizzled.
// W1: 8 chunks of [256 x 64] SW128 (32 KB each) = 256 KB.
// W2: 8 chunks of [256 x 32] SW64  (16 KB each) = 128 KB.
// ============================================================================
__device__ __align__(16) unsigned char g_w1[262144];
__device__ __align__(16) unsigned char g_w2[131072];
__device__ int g_idx64;   // 1 if dst/src are int64, 0 if int32

// ============================================================================
// Helpers (plain sm_103-level PTX: ldmatrix / mma.sync / cp.async only)
// ============================================================================
__device__ __forceinline__ uint32_t smem_to_u32(const void* p) {
    uint32_t a;
    asm("{ .reg .u64 t; cvta.to.shared.u64 t, %1; cvt.u32.u64 %0, t; }"
        : "=r"(a) : "l"(p));
    return a;
}

#define SWZ128(o) ((o) ^ (((o) >> 3) & 0x70))
#define SWZ64(o)  ((o) ^ (((o) >> 3) & 0x30))

#define CP16(dst, src) \
    asm volatile("cp.async.cg.shared.global [%0], [%1], 16;" \
        :: "r"(dst), "l"(src))
#define CP_COMMIT() asm volatile("cp.async.commit_group;")
#define CP_WAIT0()  asm volatile("cp.async.wait_group 0;" ::: "memory")
#define CP_WAIT1()  asm volatile("cp.async.wait_group 1;" ::: "memory")

// ldmatrix.x4 from SW128 image with 128-B rows (64 fp16 k-cols)
__device__ __forceinline__ void ldsm4(uint32_t* d, uint32_t base, int r0,
                                      int ks, int lane) {
    int r = r0 + (lane & 15);
    uint32_t byte = (uint32_t)(r * 128 + ks * 32 + (lane >> 4) * 16);
    uint32_t addr = base + SWZ128(byte);
    asm volatile("ldmatrix.sync.aligned.m8n8.x4.shared.b16 {%0,%1,%2,%3}, [%4];"
        : "=r"(d[0]), "=r"(d[1]), "=r"(d[2]), "=r"(d[3]) : "r"(addr));
}

// ldmatrix.x4 from SW64 image with 64-B rows (32 fp16 k-cols)
__device__ __forceinline__ void ldsm4_64(uint32_t* d, uint32_t base, int r0,
                                         int ks16, int lane) {
    int r = r0 + (lane & 15);
    uint32_t byte = (uint32_t)(r * 64 + ks16 * 32 + (lane >> 4) * 16);
    uint32_t addr = base + SWZ64(byte);
    asm volatile("ldmatrix.sync.aligned.m8n8.x4.shared.b16 {%0,%1,%2,%3}, [%4];"
        : "=r"(d[0]), "=r"(d[1]), "=r"(d[2]), "=r"(d[3]) : "r"(addr));
}

__device__ __forceinline__ void mma16816(float* c, const uint32_t* a,
                                         uint32_t b0, uint32_t b1) {
    asm volatile(
        "mma.sync.aligned.m16n8k16.row.col.f32.f16.f16.f32 "
        "{%0,%1,%2,%3}, {%4,%5,%6,%7}, {%8,%9}, {%0,%1,%2,%3};"
        : "+f"(c[0]), "+f"(c[1]), "+f"(c[2]), "+f"(c[3])
        : "r"(a[0]), "r"(a[1]), "r"(a[2]), "r"(a[3]), "r"(b0), "r"(b1));
}

__device__ __forceinline__ uint32_t pack_h2(float a, float b) {
    __half2 h = __floats2half2_rn(a, b);   // a -> low half (k even)
    return *reinterpret_cast<uint32_t*>(&h);
}

// ============================================================================
// Prologue 1: index dtype detection (values < 100000 -> int64 buffers have
// all odd 32-bit words zero).
// ============================================================================
__global__ void detect_idx_kernel(const int* __restrict__ p) {
    __shared__ int flag;
    if (threadIdx.x == 0) flag = 1;
    __syncthreads();
    if (p[2 * threadIdx.x + 1] != 0) flag = 0;
    __syncthreads();
    if (threadIdx.x == 0) g_idx64 = flag;
}

// ============================================================================
// Prologue 2: W1/W2 ([K][N] row-major) -> fp16 [N][K] swizzled images.
// ============================================================================
__global__ void prep_weights_kernel(const float* __restrict__ W1,
                                    const float* __restrict__ W2) {
    int t = blockIdx.x * blockDim.x + threadIdx.x;
    if (t < 512 * 256) {
        int k = t >> 8, n = t & 255;
        __half h = __float2half_rn(W1[t]);
        uint32_t off = (uint32_t)(n * 128 + (k & 63) * 2);
        uint32_t a = SWZ128(off) + (uint32_t)(k >> 6) * 32768u;
        *(unsigned short*)(g_w1 + a) = *(unsigned short*)&h;
    } else {
        int t2 = t - 512 * 256;
        if (t2 < 256 * 256) {
            int k = t2 >> 8, n = t2 & 255;
            __half h = __float2half_rn(W2[t2]);
            uint32_t off = (uint32_t)(n * 64 + (k & 31) * 2);
            uint32_t a = SWZ64(off) + (uint32_t)(k >> 5) * 16384u;
            *(unsigned short*)(g_w2 + a) = *(unsigned short*)&h;
        }
    }
}

// ============================================================================
// Main fused kernel. CTA = 64 pairs, 8 warps, warp tile 32(M) x 64(N),
// 2 CTAs/SM. Single-term fp16 GEMMs via mma.sync, pipelined fills.
// ============================================================================
__global__ void __launch_bounds__(THREADS, 2)
edge_mlp_kernel(const float* __restrict__ h_nodes,
                const void*  __restrict__ dstp,
                const void*  __restrict__ srcp,
                const float* __restrict__ W3,
                float*       __restrict__ out) {
    extern __shared__ unsigned char smem[];
    uint32_t smem_base = smem_to_u32(smem);
    int tid  = threadIdx.x;
    int lane = tid & 31;
    int wid  = tid >> 5;
    int warp_m = wid & 1;    // 0..1 -> 32 M-rows each
    int warp_n = wid >> 1;   // 0..3 -> 64 N-cols each

    // ---- indices, W3, zero out-accum ----
    int gbase = blockIdx.x * TILE_M;
    int* sm_idx = (int*)(smem + OFF_IDX);
    bool i64 = (g_idx64 != 0);
    if (tid < 64) {
        sm_idx[tid] = i64 ? (int)((const long long*)dstp)[gbase + tid]
                          : ((const int*)dstp)[gbase + tid];
    } else if (tid < 128) {
        int t = tid - 64;
        sm_idx[64 + t] = i64 ? (int)((const long long*)srcp)[gbase + t]
                             : ((const int*)srcp)[gbase + t];
    }
    float* w3s = (float*)(smem + OFF_W3);
    w3s[tid] = W3[tid];
    w3s[tid + 256] = W3[tid + 256];
    float* sm_out = (float*)(smem + OFF_OUT);
    if (tid < 128) sm_out[tid] = 0.0f;
    __syncthreads();

    float acc[2][8][4];
    #pragma unroll
    for (int a = 0; a < 2; a++)
        #pragma unroll
        for (int b = 0; b < 8; b++)
            #pragma unroll
            for (int c = 0; c < 4; c++) acc[a][b][c] = 0.0f;

    int m_row = tid >> 2;   // 0..63 (gather row)
    int part  = tid & 3;    // 16 floats each

    // ------------------------------------------------------------------
    // GEMM1: D0[64,256] = concat(h[dst],h[src])[64,512] @ W1
    // Pipelined: A gather prefetched to regs, B via cp.async, 2 stages.
    // ------------------------------------------------------------------
    float4 pref[4];
    {   // prologue: A(0) -> regs, B(0) -> stage 0
        int idx = sm_idx[m_row];
        const float4* rp = (const float4*)(h_nodes + (size_t)idx * 256) + part * 4;
        #pragma unroll
        for (int q = 0; q < 4; q++) pref[q] = rp[q];
        uint32_t db = smem_base + OFF_STAGE + ST_B;
        #pragma unroll
        for (int i = 0; i < 8; i++) {
            uint32_t o = (uint32_t)(tid * 16 + i * 4096);
            CP16(db + o, g_w1 + o);
        }
        CP_COMMIT();
    }

    for (int kc = 0; kc < 8; kc++) {
        int s = kc & 1;
        uint32_t stage = OFF_STAGE + (uint32_t)s * STAGE_BYTES;
        // convert + STS A chunk from prefetch regs
        {
            unsigned char* ap = smem + stage + ST_A;
            #pragma unroll
            for (int qq = 0; qq < 2; qq++) {
                float4 v0 = pref[2 * qq];
                float4 v1 = pref[2 * qq + 1];
                int j0 = part * 16 + qq * 8;
                uint32_t sw = SWZ128((uint32_t)(m_row * 128 + j0 * 2));
                uint4 st;
                st.x = pack_h2(v0.x, v0.y);
                st.y = pack_h2(v0.z, v0.w);
                st.z = pack_h2(v1.x, v1.y);
                st.w = pack_h2(v1.z, v1.w);
                *(uint4*)(ap + sw) = st;
            }
        }
        // prefetch next chunk (A regs + B cp.async into other stage)
        if (kc < 7) {
            int kn = kc + 1;
            int idx = sm_idx[((kn < 4) ? 0 : 64) + m_row];
            const float4* rp = (const float4*)(h_nodes + (size_t)idx * 256 +
                                               (kn & 3) * 64) + part * 4;
            #pragma unroll
            for (int q = 0; q < 4; q++) pref[q] = rp[q];
            uint32_t db = smem_base + OFF_STAGE +
                          (uint32_t)(s ^ 1) * STAGE_BYTES + ST_B;
            const unsigned char* gw = g_w1 + kn * 32768;
            #pragma unroll
            for (int i = 0; i < 8; i++) {
                uint32_t o = (uint32_t)(tid * 16 + i * 4096);
                CP16(db + o, gw + o);
            }
            CP_COMMIT();
            CP_WAIT1();    // current chunk's B group done
        } else {
            CP_WAIT0();
        }
        __syncthreads();
        // compute 64-k chunk (single fp16 term)
        uint32_t aB = smem_base + stage + ST_A;
        uint32_t bB = smem_base + stage + ST_B;
        #pragma unroll
        for (int ks = 0; ks < 4; ks++) {
            uint32_t ah[2][4];
            ldsm4(ah[0], aB, warp_m * 32,      ks, lane);
            ldsm4(ah[1], aB, warp_m * 32 + 16, ks, lane);
            #pragma unroll
            for (int ng = 0; ng < 4; ng++) {
                uint32_t bf[4];
                ldsm4(bf, bB, warp_n * 64 + ng * 16, ks, lane);
                mma16816(acc[0][ng * 2 + 0], ah[0], bf[0], bf[2]);
                mma16816(acc[0][ng * 2 + 1], ah[0], bf[1], bf[3]);
                mma16816(acc[1][ng * 2 + 0], ah[1], bf[0], bf[2]);
                mma16816(acc[1][ng * 2 + 1], ah[1], bf[1], bf[3]);
            }
        }
        __syncthreads();
    }

    // Prefetch GEMM2 B chunk 0 (overlaps epilogue 1). Stage region's last
    // readers synced above.
    {
        uint32_t db = smem_base + OFF_B2;
        #pragma unroll
        for (int i = 0; i < 4; i++) {
            uint32_t o = (uint32_t)(tid * 16 + i * 4096);
            CP16(db + o, g_w2 + o);
        }
        CP_COMMIT();
    }

    // ------------------------------------------------------------------
    // Epilogue 1: ReLU + fp16 convert -> X1 (4 SW128 tiles of [64 x 64])
    // ------------------------------------------------------------------
    {
        unsigned char* x1 = smem + OFF_X1 + warp_n * 8192;
        int r0 = warp_m * 32 + (lane >> 2);
        int qb = 2 * (lane & 3);
        #pragma unroll
        for (int mf = 0; mf < 2; mf++) {
            #pragma unroll
            for (int nf = 0; nf < 8; nf++) {
                int qq = nf * 8 + qb;
                #pragma unroll
                for (int half = 0; half < 2; half++) {
                    float v0 = acc[mf][nf][half * 2 + 0];
                    float v1 = acc[mf][nf][half * 2 + 1];
                    v0 = v0 > 0.f ? v0 : 0.f;
                    v1 = v1 > 0.f ? v1 : 0.f;
                    int row = r0 + mf * 16 + half * 8;
                    uint32_t sw = SWZ128((uint32_t)(row * 128 + qq * 2));
                    *(uint32_t*)(x1 + sw) = pack_h2(v0, v1);
                }
            }
        }
    }

    // re-zero accumulators for GEMM2
    #pragma unroll
    for (int a = 0; a < 2; a++)
        #pragma unroll
        for (int b = 0; b < 8; b++)
            #pragma unroll
            for (int c = 0; c < 4; c++) acc[a][b][c] = 0.0f;

    // ------------------------------------------------------------------
    // GEMM2: D1[64,256] = X1[64,256] @ W2. 8 chunks of k=32 (SW64 B),
    // double-buffered cp.async pipeline.
    // ------------------------------------------------------------------
    for (int kc = 0; kc < 8; kc++) {
        int s = kc & 1;
        if (kc < 7) {
            int kn = kc + 1;
            uint32_t db = smem_base + OFF_B2 + (uint32_t)(s ^ 1) * 16384u;
            const unsigned char* gw = g_w2 + kn * 16384;
            #pragma unroll
            for (int i = 0; i < 4; i++) {
                uint32_t o = (uint32_t)(tid * 16 + i * 4096);
                CP16(db + o, gw + o);
            }
            CP_COMMIT();
            CP_WAIT1();
        } else {
            CP_WAIT0();
        }
        __syncthreads();   // publishes X1 (kc==0) and current B2 stage
        int tile = kc >> 1;
        uint32_t aB = smem_base + OFF_X1 + (uint32_t)tile * 8192u;
        uint32_t bB = smem_base + OFF_B2 + (uint32_t)s * 16384u;
        #pragma unroll
        for (int ks16 = 0; ks16 < 2; ks16++) {
            int kwin = (kc & 1) * 2 + ks16;   // 16-col slot in SW128 tile
            uint32_t ah[2][4];
            ldsm4(ah[0], aB, warp_m * 32,      kwin, lane);
            ldsm4(ah[1], aB, warp_m * 32 + 16, kwin, lane);
            #pragma unroll
            for (int ng = 0; ng < 4; ng++) {
                uint32_t bf[4];
                ldsm4_64(bf, bB, warp_n * 64 + ng * 16, ks16, lane);
                mma16816(acc[0][ng * 2 + 0], ah[0], bf[0], bf[2]);
                mma16816(acc[0][ng * 2 + 1], ah[0], bf[1], bf[3]);
                mma16816(acc[1][ng * 2 + 0], ah[1], bf[0], bf[2]);
                mma16816(acc[1][ng * 2 + 1], ah[1], bf[1], bf[3]);
            }
        }
        __syncthreads();
    }

    // ------------------------------------------------------------------
    // Epilogue 2 (fused GEMM3): out[m,:] = ReLU(D1[m,:]) @ W3[256,2]
    // ------------------------------------------------------------------
    {
        float p[4][2];
        #pragma unroll
        for (int r = 0; r < 4; r++) { p[r][0] = 0.f; p[r][1] = 0.f; }
        int qb = 2 * (lane & 3);
        #pragma unroll
        for (int mf = 0; mf < 2; mf++) {
            #pragma unroll
            for (int nf = 0; nf < 8; nf++) {
                #pragma unroll
                for (int i = 0; i < 4; i++) {
                    float v = acc[mf][nf][i];
                    v = v > 0.f ? v : 0.f;
                    int rsel = mf * 2 + (i >> 1);
                    int n = warp_n * 64 + nf * 8 + qb + (i & 1);
                    p[rsel][0] = fmaf(v, w3s[2 * n],     p[rsel][0]);
                    p[rsel][1] = fmaf(v, w3s[2 * n + 1], p[rsel][1]);
                }
            }
        }
        #pragma unroll
        for (int r = 0; r < 4; r++) {
            #pragma unroll
            for (int c = 0; c < 2; c++) {
                p[r][c] += __shfl_xor_sync(0xffffffffu, p[r][c], 1);
                p[r][c] += __shfl_xor_sync(0xffffffffu, p[r][c], 2);
            }
        }
        if ((lane & 3) == 0) {
            #pragma unroll
            for (int r = 0; r < 4; r++) {
                int row = warp_m * 32 + (r >> 1) * 16 + (r & 1) * 8 + (lane >> 2);
                atomicAdd(&sm_out[row * 2 + 0], p[r][0]);
                atomicAdd(&sm_out[row * 2 + 1], p[r][1]);
            }
        }
    }
    __syncthreads();
    if (tid < 128)
        out[(size_t)gbase * 2 + tid] = sm_out[tid];
}

// ============================================================================
// Launch
// ============================================================================
extern "C" void kernel_launch(void* const* d_in, const int* in_sizes, int n_in,
                              void* d_out, int out_size) {
    const float* h_nodes = (const float*)d_in[0];
    const void*  dstp    = d_in[1];
    const void*  srcp    = d_in[2];
    const float* W1      = (const float*)d_in[3];
    const float* W2      = (const float*)d_in[4];
    const float* W3      = (const float*)d_in[5];
    float*       out     = (float*)d_out;

    detect_idx_kernel<<<1, 128>>>((const int*)dstp);
    prep_weights_kernel<<<768, 256>>>(W1, W2);

    cudaFuncSetAttribute(edge_mlp_kernel,
                         cudaFuncAttributeMaxDynamicSharedMemorySize, SMEM_TOTAL);
    edge_mlp_kernel<<<NTILES, THREADS, SMEM_TOTAL>>>(h_nodes, dstp, srcp, W3, out);
}

// round 11
// speedup vs baseline: 2.8213x; 1.0514x over previous
#include <cuda_runtime.h>
#include <cuda_fp16.h>
#include <stdint.h>

// ============================================================================
// Problem constants
// ============================================================================
#define P_PAIRS   524288
#define TILE_M    64
#define NTILES    (P_PAIRS / TILE_M)   // 8192
#define THREADS   256

// ---------------- SMEM layout (100 KB -> 2 CTAs/SM) --------------------------
#define OFF_IDX     0         // 128 int32
#define OFF_W3      1024      // 512 floats
#define OFF_OUT     3072      // 128 floats
// GEMM1: two 40 KB stages
#define OFF_STAGE   4096
#define STAGE_BYTES 40960
#define ST_A        0         // [64 x 64] fp16, 8 KB
#define ST_B        8192      // [256 x 64] fp16, 32 KB
// GEMM2 (reuses region after GEMM1):
#define OFF_X1      4096      // 4 tiles x [64 x 64] fp16 = 32 KB
#define OFF_B2      36864     // 2 stages x 32 KB = 64 KB
#define SMEM_TOTAL  102400

// ============================================================================
// Device scratch: weights as fp16, transposed to [N][K], pre-swizzled SW128.
// W1: 8 chunks of [256 x 64] (32 KB each). W2: 4 chunks of [256 x 64].
// ============================================================================
__device__ __align__(16) unsigned char g_w1[262144];
__device__ __align__(16) unsigned char g_w2[131072];

// ============================================================================
// Helpers (plain sm_103-level PTX: ldmatrix / mma.sync / cp.async only)
// ============================================================================
__device__ __forceinline__ uint32_t smem_to_u32(const void* p) {
    uint32_t a;
    asm("{ .reg .u64 t; cvta.to.shared.u64 t, %1; cvt.u32.u64 %0, t; }"
        : "=r"(a) : "l"(p));
    return a;
}

#define SWZ128(o) ((o) ^ (((o) >> 3) & 0x70))

#define CP16(dst, src) \
    asm volatile("cp.async.cg.shared.global [%0], [%1], 16;" \
        :: "r"(dst), "l"(src))
#define CP_COMMIT() asm volatile("cp.async.commit_group;")
#define CP_WAIT0()  asm volatile("cp.async.wait_group 0;" ::: "memory")

// ldmatrix.x4: 16x16 fp16 tile from SW128 image with 128-B rows
__device__ __forceinline__ void ldsm4(uint32_t* d, uint32_t base, int r0,
                                      int ks, int lane) {
    int r = r0 + (lane & 15);
    uint32_t byte = (uint32_t)(r * 128 + ks * 32 + (lane >> 4) * 16);
    uint32_t addr = base + SWZ128(byte);
    asm volatile("ldmatrix.sync.aligned.m8n8.x4.shared.b16 {%0,%1,%2,%3}, [%4];"
        : "=r"(d[0]), "=r"(d[1]), "=r"(d[2]), "=r"(d[3]) : "r"(addr));
}

__device__ __forceinline__ void mma16816(float* c, const uint32_t* a,
                                         uint32_t b0, uint32_t b1) {
    asm volatile(
        "mma.sync.aligned.m16n8k16.row.col.f32.f16.f16.f32 "
        "{%0,%1,%2,%3}, {%4,%5,%6,%7}, {%8,%9}, {%0,%1,%2,%3};"
        : "+f"(c[0]), "+f"(c[1]), "+f"(c[2]), "+f"(c[3])
        : "r"(a[0]), "r"(a[1]), "r"(a[2]), "r"(a[3]), "r"(b0), "r"(b1));
}

__device__ __forceinline__ uint32_t pack_h2(float a, float b) {
    __half2 h = __floats2half2_rn(a, b);   // a -> low half (k even)
    return *reinterpret_cast<uint32_t*>(&h);
}

// ============================================================================
// 64-k-chunk compute, register-pipelined: B fragment double-buffered so the
// next ldsm is in flight while current fragments feed the tensor pipe.
// ============================================================================
__device__ __forceinline__ void mma_chunk(float (&acc)[2][8][4], uint32_t aB,
                                          uint32_t bB, int warp_m, int warp_n,
                                          int lane) {
    uint32_t a0[4], a1[4], a0n[4], a1n[4], bc[4], bn[4];
    ldsm4(a0, aB, warp_m * 32,      0, lane);
    ldsm4(a1, aB, warp_m * 32 + 16, 0, lane);
    ldsm4(bc, bB, warp_n * 64,      0, lane);
    #pragma unroll
    for (int ks = 0; ks < 4; ks++) {
        #pragma unroll
        for (int ng = 0; ng < 4; ng++) {
            if (ng < 3) {
                ldsm4(bn, bB, warp_n * 64 + (ng + 1) * 16, ks, lane);
            } else if (ks < 3) {
                ldsm4(a0n, aB, warp_m * 32,      ks + 1, lane);
                ldsm4(a1n, aB, warp_m * 32 + 16, ks + 1, lane);
                ldsm4(bn,  bB, warp_n * 64,      ks + 1, lane);
            }
            mma16816(acc[0][ng * 2 + 0], a0, bc[0], bc[2]);
            mma16816(acc[0][ng * 2 + 1], a0, bc[1], bc[3]);
            mma16816(acc[1][ng * 2 + 0], a1, bc[0], bc[2]);
            mma16816(acc[1][ng * 2 + 1], a1, bc[1], bc[3]);
            if (!(ng == 3 && ks == 3)) {
                #pragma unroll
                for (int i = 0; i < 4; i++) bc[i] = bn[i];
            }
            if (ng == 3 && ks < 3) {
                #pragma unroll
                for (int i = 0; i < 4; i++) { a0[i] = a0n[i]; a1[i] = a1n[i]; }
            }
        }
    }
}

// ============================================================================
// Prologue: W1/W2 ([K][N] row-major) -> fp16 [N][K] SW128 swizzled images.
// ============================================================================
__global__ void prep_weights_kernel(const float* __restrict__ W1,
                                    const float* __restrict__ W2) {
    int t = blockIdx.x * blockDim.x + threadIdx.x;
    if (t < 512 * 256) {
        int k = t >> 8, n = t & 255;
        __half h = __float2half_rn(W1[t]);
        uint32_t off = (uint32_t)(n * 128 + (k & 63) * 2);
        uint32_t a = SWZ128(off) + (uint32_t)(k >> 6) * 32768u;
        *(unsigned short*)(g_w1 + a) = *(unsigned short*)&h;
    } else {
        int t2 = t - 512 * 256;
        if (t2 < 256 * 256) {
            int k = t2 >> 8, n = t2 & 255;
            __half h = __float2half_rn(W2[t2]);
            uint32_t off = (uint32_t)(n * 128 + (k & 63) * 2);
            uint32_t a = SWZ128(off) + (uint32_t)(k >> 6) * 32768u;
            *(unsigned short*)(g_w2 + a) = *(unsigned short*)&h;
        }
    }
}

// ============================================================================
// Main fused kernel. CTA = 64 pairs, 8 warps, warp tile 32(M) x 64(N),
// 2 CTAs/SM. fp16 GEMMs via mma.sync; one barrier per k-chunk.
// ============================================================================
__global__ void __launch_bounds__(THREADS, 2)
edge_mlp_kernel(const float* __restrict__ h_nodes,
                const void*  __restrict__ dstp,
                const void*  __restrict__ srcp,
                const float* __restrict__ W3,
                float*       __restrict__ out) {
    extern __shared__ unsigned char smem[];
    uint32_t smem_base = smem_to_u32(smem);
    int tid  = threadIdx.x;
    int lane = tid & 31;
    int wid  = tid >> 5;
    int warp_m = wid & 1;    // 0..1 -> 32 M-rows each
    int warp_n = wid >> 1;   // 0..3 -> 64 N-cols each

    int gbase = blockIdx.x * TILE_M;

    // ---- per-CTA index-dtype detection (values < 100000: int64 buffers
    // have all odd 32-bit words zero; int32 random values make this
    // astronomically unlikely across 128 samples) ----
    int odd = 0;
    if (tid < 64)       odd = ((const int*)dstp)[2 * (gbase + tid) + 1];
    else if (tid < 128) odd = ((const int*)srcp)[2 * (gbase + tid - 64) + 1];
    bool i64 = (__syncthreads_or(odd != 0) == 0);

    // ---- indices, W3, zero out-accum ----
    int* sm_idx = (int*)(smem + OFF_IDX);
    if (tid < 64) {
        sm_idx[tid] = i64 ? (int)((const long long*)dstp)[gbase + tid]
                          : ((const int*)dstp)[gbase + tid];
    } else if (tid < 128) {
        int t = tid - 64;
        sm_idx[64 + t] = i64 ? (int)((const long long*)srcp)[gbase + t]
                             : ((const int*)srcp)[gbase + t];
    }
    float* w3s = (float*)(smem + OFF_W3);
    w3s[tid] = W3[tid];
    w3s[tid + 256] = W3[tid + 256];
    float* sm_out = (float*)(smem + OFF_OUT);
    if (tid < 128) sm_out[tid] = 0.0f;
    __syncthreads();

    float acc[2][8][4];
    #pragma unroll
    for (int a = 0; a < 2; a++)
        #pragma unroll
        for (int b = 0; b < 8; b++)
            #pragma unroll
            for (int c = 0; c < 4; c++) acc[a][b][c] = 0.0f;

    int m_row = tid >> 2;   // 0..63 (gather row)
    int part  = tid & 3;    // 16 floats each

    // ------------------------------------------------------------------
    // GEMM1: D0[64,256] = concat(h[dst],h[src])[64,512] @ W1
    // One sync per k-chunk; fills for kc+1 issued after sync(kc):
    //   cp B(kc+1) right away, STS A(kc+1) after compute (hides LDG).
    // ------------------------------------------------------------------
    float4 pref[4];
    {   // prologue: A(0) -> stage0, B(0) -> stage0
        int idx = sm_idx[m_row];
        const float4* rp = (const float4*)(h_nodes + (size_t)idx * 256) + part * 4;
        #pragma unroll
        for (int q = 0; q < 4; q++) pref[q] = rp[q];
        unsigned char* ap = smem + OFF_STAGE + ST_A;
        #pragma unroll
        for (int qq = 0; qq < 2; qq++) {
            float4 v0 = pref[2 * qq];
            float4 v1 = pref[2 * qq + 1];
            int j0 = part * 16 + qq * 8;
            uint32_t sw = SWZ128((uint32_t)(m_row * 128 + j0 * 2));
            uint4 st;
            st.x = pack_h2(v0.x, v0.y);
            st.y = pack_h2(v0.z, v0.w);
            st.z = pack_h2(v1.x, v1.y);
            st.w = pack_h2(v1.z, v1.w);
            *(uint4*)(ap + sw) = st;
        }
        uint32_t db = smem_base + OFF_STAGE + ST_B;
        #pragma unroll
        for (int i = 0; i < 8; i++) {
            uint32_t o = (uint32_t)(tid * 16 + i * 4096);
            CP16(db + o, g_w1 + o);
        }
        CP_COMMIT();
    }

    for (int kc = 0; kc < 8; kc++) {
        int s = kc & 1;
        uint32_t stage  = OFF_STAGE + (uint32_t)s * STAGE_BYTES;
        uint32_t nstage = OFF_STAGE + (uint32_t)(s ^ 1) * STAGE_BYTES;
        CP_WAIT0();
        __syncthreads();   // publishes A(kc)/B(kc); all compute(kc-1) done
        if (kc < 7) {
            int kn = kc + 1;
            // B(kc+1) via cp.async into the alternate stage
            uint32_t db = smem_base + nstage + ST_B;
            const unsigned char* gw = g_w1 + kn * 32768;
            #pragma unroll
            for (int i = 0; i < 8; i++) {
                uint32_t o = (uint32_t)(tid * 16 + i * 4096);
                CP16(db + o, gw + o);
            }
            CP_COMMIT();
            // A(kc+1) gather LDG -> regs (consumed by STS after compute)
            int idx = sm_idx[((kn < 4) ? 0 : 64) + m_row];
            const float4* rp = (const float4*)(h_nodes + (size_t)idx * 256 +
                                               (kn & 3) * 64) + part * 4;
            #pragma unroll
            for (int q = 0; q < 4; q++) pref[q] = rp[q];
        }
        // compute current chunk
        mma_chunk(acc, smem_base + stage + ST_A, smem_base + stage + ST_B,
                  warp_m, warp_n, lane);
        // STS A(kc+1) into alternate stage (LDG latency hidden by compute)
        if (kc < 7) {
            unsigned char* ap = smem + nstage + ST_A;
            #pragma unroll
            for (int qq = 0; qq < 2; qq++) {
                float4 v0 = pref[2 * qq];
                float4 v1 = pref[2 * qq + 1];
                int j0 = part * 16 + qq * 8;
                uint32_t sw = SWZ128((uint32_t)(m_row * 128 + j0 * 2));
                uint4 st;
                st.x = pack_h2(v0.x, v0.y);
                st.y = pack_h2(v0.z, v0.w);
                st.z = pack_h2(v1.x, v1.y);
                st.w = pack_h2(v1.z, v1.w);
                *(uint4*)(ap + sw) = st;
            }
        }
    }

    // All compute(7) reads stage1 only; wait for every warp before B2 cp
    // (B2 region overlaps stage1). X1 region (== stage0) is already safe.
    __syncthreads();

    // Prefetch GEMM2 B chunk 0 (overlaps epilogue 1)
    {
        uint32_t db = smem_base + OFF_B2;
        #pragma unroll
        for (int i = 0; i < 8; i++) {
            uint32_t o = (uint32_t)(tid * 16 + i * 4096);
            CP16(db + o, g_w2 + o);
        }
        CP_COMMIT();
    }

    // ------------------------------------------------------------------
    // Epilogue 1: ReLU + fp16 convert -> X1 (4 SW128 tiles of [64 x 64])
    // ------------------------------------------------------------------
    {
        unsigned char* x1 = smem + OFF_X1 + warp_n * 8192;
        int r0 = warp_m * 32 + (lane >> 2);
        int qb = 2 * (lane & 3);
        #pragma unroll
        for (int mf = 0; mf < 2; mf++) {
            #pragma unroll
            for (int nf = 0; nf < 8; nf++) {
                int qq = nf * 8 + qb;
                #pragma unroll
                for (int half = 0; half < 2; half++) {
                    float v0 = acc[mf][nf][half * 2 + 0];
                    float v1 = acc[mf][nf][half * 2 + 1];
                    v0 = v0 > 0.f ? v0 : 0.f;
                    v1 = v1 > 0.f ? v1 : 0.f;
                    int row = r0 + mf * 16 + half * 8;
                    uint32_t sw = SWZ128((uint32_t)(row * 128 + qq * 2));
                    *(uint32_t*)(x1 + sw) = pack_h2(v0, v1);
                }
            }
        }
    }

    // re-zero accumulators for GEMM2
    #pragma unroll
    for (int a = 0; a < 2; a++)
        #pragma unroll
        for (int b = 0; b < 8; b++)
            #pragma unroll
            for (int c = 0; c < 4; c++) acc[a][b][c] = 0.0f;

    // ------------------------------------------------------------------
    // GEMM2: D1[64,256] = X1[64,256] @ W2. 4 chunks of k=64 (SW128),
    // double-buffered cp.async, one sync per chunk.
    // ------------------------------------------------------------------
    for (int kc = 0; kc < 4; kc++) {
        int s = kc & 1;
        CP_WAIT0();
        __syncthreads();   // publishes X1 (kc==0) and B2(kc)
        if (kc < 3) {
            uint32_t db = smem_base + OFF_B2 + (uint32_t)(s ^ 1) * 32768u;
            const unsigned char* gw = g_w2 + (kc + 1) * 32768;
            #pragma unroll
            for (int i = 0; i < 8; i++) {
                uint32_t o = (uint32_t)(tid * 16 + i * 4096);
                CP16(db + o, gw + o);
            }
            CP_COMMIT();
        }
        mma_chunk(acc, smem_base + OFF_X1 + (uint32_t)kc * 8192u,
                  smem_base + OFF_B2 + (uint32_t)s * 32768u,
                  warp_m, warp_n, lane);
    }

    // ------------------------------------------------------------------
    // Epilogue 2 (fused GEMM3): out[m,:] = ReLU(D1[m,:]) @ W3[256,2]
    // ------------------------------------------------------------------
    {
        float p[4][2];
        #pragma unroll
        for (int r = 0; r < 4; r++) { p[r][0] = 0.f; p[r][1] = 0.f; }
        int qb = 2 * (lane & 3);
        #pragma unroll
        for (int mf = 0; mf < 2; mf++) {
            #pragma unroll
            for (int nf = 0; nf < 8; nf++) {
                #pragma unroll
                for (int i = 0; i < 4; i++) {
                    float v = acc[mf][nf][i];
                    v = v > 0.f ? v : 0.f;
                    int rsel = mf * 2 + (i >> 1);
                    int n = warp_n * 64 + nf * 8 + qb + (i & 1);
                    p[rsel][0] = fmaf(v, w3s[2 * n],     p[rsel][0]);
                    p[rsel][1] = fmaf(v, w3s[2 * n + 1], p[rsel][1]);
                }
            }
        }
        #pragma unroll
        for (int r = 0; r < 4; r++) {
            #pragma unroll
            for (int c = 0; c < 2; c++) {
                p[r][c] += __shfl_xor_sync(0xffffffffu, p[r][c], 1);
                p[r][c] += __shfl_xor_sync(0xffffffffu, p[r][c], 2);
            }
        }
        if ((lane & 3) == 0) {
            #pragma unroll
            for (int r = 0; r < 4; r++) {
                int row = warp_m * 32 + (r >> 1) * 16 + (r & 1) * 8 + (lane >> 2);
                atomicAdd(&sm_out[row * 2 + 0], p[r][0]);
                atomicAdd(&sm_out[row * 2 + 1], p[r][1]);
            }
        }
    }
    __syncthreads();
    if (tid < 128)
        out[(size_t)gbase * 2 + tid] = sm_out[tid];
}

// ============================================================================
// Launch
// ============================================================================
extern "C" void kernel_launch(void* const* d_in, const int* in_sizes, int n_in,
                              void* d_out, int out_size) {
    const float* h_nodes = (const float*)d_in[0];
    const void*  dstp    = d_in[1];
    const void*  srcp    = d_in[2];
    const float* W1      = (const float*)d_in[3];
    const float* W2      = (const float*)d_in[4];
    const float* W3      = (const float*)d_in[5];
    float*       out     = (float*)d_out;

    prep_weights_kernel<<<768, 256>>>(W1, W2);

    cudaFuncSetAttribute(edge_mlp_kernel,
                         cudaFuncAttributeMaxDynamicSharedMemorySize, SMEM_TOTAL);
    edge_mlp_kernel<<<NTILES, THREADS, SMEM_TOTAL>>>(h_nodes, dstp, srcp, W3, out);
}

// round 12
// speedup vs baseline: 3.3749x; 1.1962x over previous
#include <cuda_runtime.h>
#include <cuda_fp16.h>
#include <stdint.h>

// ============================================================================
// Problem constants
// ============================================================================
#define P_PAIRS   524288
#define NUM_NODES 100000
#define TILE_M    64
#define NTILES    (P_PAIRS / TILE_M)   // 8192
#define THREADS   256

// ---------------- SMEM layout (100 KB -> 2 CTAs/SM) --------------------------
#define OFF_IDX     0         // 128 int32
#define OFF_W3      1024      // 512 floats
#define OFF_OUT     3072      // 128 floats
// GEMM1: two 40 KB stages
#define OFF_STAGE   4096
#define STAGE_BYTES 40960
#define ST_A        0         // [64 x 64] fp16, 8 KB
#define ST_B        8192      // [256 x 64] fp16, 32 KB
// GEMM2 (reuses region after GEMM1):
#define OFF_X1      4096      // 4 tiles x [64 x 64] fp16 = 32 KB
#define OFF_B2      36864     // 2 stages x 32 KB = 64 KB
#define SMEM_TOTAL  102400

// ============================================================================
// Device scratch:
//  g_h16 : h_nodes pre-converted to fp16, row-major [node][256] (512 B/row)
//  g_w1/g_w2 : weights fp16, [N][K] SW128-swizzled 64-k-chunk tile images
// ============================================================================
__device__ __align__(16) __half g_h16[(size_t)NUM_NODES * 256];
__device__ __align__(16) unsigned char g_w1[262144];
__device__ __align__(16) unsigned char g_w2[131072];

// ============================================================================
// Helpers (plain sm_103-level PTX: ldmatrix / mma.sync / cp.async only)
// ============================================================================
__device__ __forceinline__ uint32_t smem_to_u32(const void* p) {
    uint32_t a;
    asm("{ .reg .u64 t; cvta.to.shared.u64 t, %1; cvt.u32.u64 %0, t; }"
        : "=r"(a) : "l"(p));
    return a;
}

#define SWZ128(o) ((o) ^ (((o) >> 3) & 0x70))

#define CP16(dst, src) \
    asm volatile("cp.async.cg.shared.global [%0], [%1], 16;" \
        :: "r"(dst), "l"(src))
#define CP_COMMIT() asm volatile("cp.async.commit_group;")
#define CP_WAIT0()  asm volatile("cp.async.wait_group 0;" ::: "memory")

// ldmatrix.x4: 16x16 fp16 tile from SW128 image with 128-B rows
__device__ __forceinline__ void ldsm4(uint32_t* d, uint32_t base, int r0,
                                      int ks, int lane) {
    int r = r0 + (lane & 15);
    uint32_t byte = (uint32_t)(r * 128 + ks * 32 + (lane >> 4) * 16);
    uint32_t addr = base + SWZ128(byte);
    asm volatile("ldmatrix.sync.aligned.m8n8.x4.shared.b16 {%0,%1,%2,%3}, [%4];"
        : "=r"(d[0]), "=r"(d[1]), "=r"(d[2]), "=r"(d[3]) : "r"(addr));
}

__device__ __forceinline__ void mma16816(float* c, const uint32_t* a,
                                         uint32_t b0, uint32_t b1) {
    asm volatile(
        "mma.sync.aligned.m16n8k16.row.col.f32.f16.f16.f32 "
        "{%0,%1,%2,%3}, {%4,%5,%6,%7}, {%8,%9}, {%0,%1,%2,%3};"
        : "+f"(c[0]), "+f"(c[1]), "+f"(c[2]), "+f"(c[3])
        : "r"(a[0]), "r"(a[1]), "r"(a[2]), "r"(a[3]), "r"(b0), "r"(b1));
}

__device__ __forceinline__ uint32_t pack_h2(float a, float b) {
    __half2 h = __floats2half2_rn(a, b);   // a -> low half
    return *reinterpret_cast<uint32_t*>(&h);
}

// ============================================================================
// 64-k-chunk compute. A fragments ks-double-buffered; B fragments prefetched
// at distance 2 so >=2 ldsm are in flight while the tensor pipe drains.
// ============================================================================
__device__ __forceinline__ void mma_chunk(float (&acc)[2][8][4], uint32_t aB,
                                          uint32_t bB, int warp_m, int warp_n,
                                          int lane) {
    uint32_t af[2][2][4];
    uint32_t bf[16][4];
    ldsm4(af[0][0], aB, warp_m * 32,      0, lane);
    ldsm4(af[0][1], aB, warp_m * 32 + 16, 0, lane);
    ldsm4(bf[0], bB, warp_n * 64 +  0, 0, lane);
    ldsm4(bf[1], bB, warp_n * 64 + 16, 0, lane);
    #pragma unroll
    for (int i = 0; i < 16; i++) {
        int ks = i >> 2, ng = i & 3;
        if (ng == 0 && ks < 3) {
            ldsm4(af[(ks + 1) & 1][0], aB, warp_m * 32,      ks + 1, lane);
            ldsm4(af[(ks + 1) & 1][1], aB, warp_m * 32 + 16, ks + 1, lane);
        }
        if (i < 14) {
            int j = i + 2;
            ldsm4(bf[j], bB, warp_n * 64 + (j & 3) * 16, j >> 2, lane);
        }
        const uint32_t* a0 = af[ks & 1][0];
        const uint32_t* a1 = af[ks & 1][1];
        mma16816(acc[0][ng * 2 + 0], a0, bf[i][0], bf[i][2]);
        mma16816(acc[0][ng * 2 + 1], a0, bf[i][1], bf[i][3]);
        mma16816(acc[1][ng * 2 + 0], a1, bf[i][0], bf[i][2]);
        mma16816(acc[1][ng * 2 + 1], a1, bf[i][1], bf[i][3]);
    }
}

// ============================================================================
// Prologue A: convert h_nodes fp32 -> fp16 image (8 elems/thread)
// ============================================================================
__global__ void prep_nodes_kernel(const float* __restrict__ h) {
    size_t i = (size_t)blockIdx.x * blockDim.x + threadIdx.x;  // 3.2M threads
    const float4* s = (const float4*)h + 2 * i;
    float4 a = s[0], b = s[1];
    uint4 o;
    o.x = pack_h2(a.x, a.y);
    o.y = pack_h2(a.z, a.w);
    o.z = pack_h2(b.x, b.y);
    o.w = pack_h2(b.z, b.w);
    ((uint4*)g_h16)[i] = o;
}

// ============================================================================
// Prologue B: W1/W2 ([K][N] row-major) -> fp16 [N][K] SW128 swizzled images.
// ============================================================================
__global__ void prep_weights_kernel(const float* __restrict__ W1,
                                    const float* __restrict__ W2) {
    int t = blockIdx.x * blockDim.x + threadIdx.x;
    if (t < 512 * 256) {
        int k = t >> 8, n = t & 255;
        __half h = __float2half_rn(W1[t]);
        uint32_t off = (uint32_t)(n * 128 + (k & 63) * 2);
        uint32_t a = SWZ128(off) + (uint32_t)(k >> 6) * 32768u;
        *(unsigned short*)(g_w1 + a) = *(unsigned short*)&h;
    } else {
        int t2 = t - 512 * 256;
        if (t2 < 256 * 256) {
            int k = t2 >> 8, n = t2 & 255;
            __half h = __float2half_rn(W2[t2]);
            uint32_t off = (uint32_t)(n * 128 + (k & 63) * 2);
            uint32_t a = SWZ128(off) + (uint32_t)(k >> 6) * 32768u;
            *(unsigned short*)(g_w2 + a) = *(unsigned short*)&h;
        }
    }
}

// ============================================================================
// Main fused kernel. CTA = 64 pairs, 8 warps, warp tile 32(M) x 64(N),
// 2 CTAs/SM. A gathered straight from g_h16 via per-thread cp.async.
// ============================================================================
__global__ void __launch_bounds__(THREADS, 2)
edge_mlp_kernel(const void*  __restrict__ dstp,
                const void*  __restrict__ srcp,
                const float* __restrict__ W3,
                float*       __restrict__ out) {
    extern __shared__ unsigned char smem[];
    uint32_t smem_base = smem_to_u32(smem);
    int tid  = threadIdx.x;
    int lane = tid & 31;
    int wid  = tid >> 5;
    int warp_m = wid & 1;    // 0..1 -> 32 M-rows each
    int warp_n = wid >> 1;   // 0..3 -> 64 N-cols each

    int gbase = blockIdx.x * TILE_M;

    // ---- per-CTA index-dtype detection (values < 100000: int64 buffers
    // have all odd 32-bit words zero) ----
    int odd = 0;
    if (tid < 64)       odd = ((const int*)dstp)[2 * (gbase + tid) + 1];
    else if (tid < 128) odd = ((const int*)srcp)[2 * (gbase + tid - 64) + 1];
    bool i64 = (__syncthreads_or(odd != 0) == 0);

    // ---- indices, W3, zero out-accum ----
    int* sm_idx = (int*)(smem + OFF_IDX);
    if (tid < 64) {
        sm_idx[tid] = i64 ? (int)((const long long*)dstp)[gbase + tid]
                          : ((const int*)dstp)[gbase + tid];
    } else if (tid < 128) {
        int t = tid - 64;
        sm_idx[64 + t] = i64 ? (int)((const long long*)srcp)[gbase + t]
                             : ((const int*)srcp)[gbase + t];
    }
    float* w3s = (float*)(smem + OFF_W3);
    w3s[tid] = W3[tid];
    w3s[tid + 256] = W3[tid + 256];
    float* sm_out = (float*)(smem + OFF_OUT);
    if (tid < 128) sm_out[tid] = 0.0f;
    __syncthreads();

    float acc[2][8][4];
    #pragma unroll
    for (int a = 0; a < 2; a++)
        #pragma unroll
        for (int b = 0; b < 8; b++)
            #pragma unroll
            for (int c = 0; c < 4; c++) acc[a][b][c] = 0.0f;

    int m_row = tid >> 2;   // 0..63 (gather row)
    int part  = tid & 3;    // 32 B each

    // A(k) gather fill: 64 rows x 128 B via per-thread cp.async (2 x 16 B)
    uint32_t a_sw0 = SWZ128((uint32_t)(m_row * 128 + part * 32));
    uint32_t a_sw1 = SWZ128((uint32_t)(m_row * 128 + part * 32 + 16));

    // ------------------------------------------------------------------
    // GEMM1: D0[64,256] = concat(h[dst],h[src])[64,512] @ W1
    // One barrier + one cp.async group per 64-k chunk, 2 stages.
    // ------------------------------------------------------------------
    {   // prologue: A(0)+B(0) -> stage 0
        int idx = sm_idx[m_row];
        const unsigned char* asrc =
            (const unsigned char*)g_h16 + (size_t)idx * 512 + part * 32;
        uint32_t ad = smem_base + OFF_STAGE + ST_A;
        CP16(ad + a_sw0, asrc);
        CP16(ad + a_sw1, asrc + 16);
        uint32_t db = smem_base + OFF_STAGE + ST_B;
        #pragma unroll
        for (int i = 0; i < 8; i++) {
            uint32_t o = (uint32_t)(tid * 16 + i * 4096);
            CP16(db + o, g_w1 + o);
        }
        CP_COMMIT();
    }

    for (int kc = 0; kc < 8; kc++) {
        int s = kc & 1;
        uint32_t stage  = OFF_STAGE + (uint32_t)s * STAGE_BYTES;
        uint32_t nstage = OFF_STAGE + (uint32_t)(s ^ 1) * STAGE_BYTES;
        CP_WAIT0();
        __syncthreads();   // A(kc)/B(kc) visible; compute(kc-1) complete
        if (kc < 7) {
            int kn = kc + 1;
            int idx = sm_idx[((kn < 4) ? 0 : 64) + m_row];
            const unsigned char* asrc = (const unsigned char*)g_h16 +
                (size_t)idx * 512 + (kn & 3) * 128 + part * 32;
            uint32_t ad = smem_base + nstage + ST_A;
            CP16(ad + a_sw0, asrc);
            CP16(ad + a_sw1, asrc + 16);
            uint32_t db = smem_base + nstage + ST_B;
            const unsigned char* gw = g_w1 + kn * 32768;
            #pragma unroll
            for (int i = 0; i < 8; i++) {
                uint32_t o = (uint32_t)(tid * 16 + i * 4096);
                CP16(db + o, gw + o);
            }
            CP_COMMIT();
        }
        mma_chunk(acc, smem_base + stage + ST_A, smem_base + stage + ST_B,
                  warp_m, warp_n, lane);
    }

    // compute(7) read stage1; B2 region overlaps stage1 -> full barrier first
    __syncthreads();

    // Prefetch GEMM2 B chunk 0 (overlaps epilogue 1)
    {
        uint32_t db = smem_base + OFF_B2;
        #pragma unroll
        for (int i = 0; i < 8; i++) {
            uint32_t o = (uint32_t)(tid * 16 + i * 4096);
            CP16(db + o, g_w2 + o);
        }
        CP_COMMIT();
    }

    // ------------------------------------------------------------------
    // Epilogue 1: ReLU + fp16 convert -> X1 (4 SW128 tiles of [64 x 64])
    // ------------------------------------------------------------------
    {
        unsigned char* x1 = smem + OFF_X1 + warp_n * 8192;
        int r0 = warp_m * 32 + (lane >> 2);
        int qb = 2 * (lane & 3);
        #pragma unroll
        for (int mf = 0; mf < 2; mf++) {
            #pragma unroll
            for (int nf = 0; nf < 8; nf++) {
                int qq = nf * 8 + qb;
                #pragma unroll
                for (int half = 0; half < 2; half++) {
                    float v0 = acc[mf][nf][half * 2 + 0];
                    float v1 = acc[mf][nf][half * 2 + 1];
                    v0 = v0 > 0.f ? v0 : 0.f;
                    v1 = v1 > 0.f ? v1 : 0.f;
                    int row = r0 + mf * 16 + half * 8;
                    uint32_t sw = SWZ128((uint32_t)(row * 128 + qq * 2));
                    *(uint32_t*)(x1 + sw) = pack_h2(v0, v1);
                }
            }
        }
    }

    // re-zero accumulators for GEMM2
    #pragma unroll
    for (int a = 0; a < 2; a++)
        #pragma unroll
        for (int b = 0; b < 8; b++)
            #pragma unroll
            for (int c = 0; c < 4; c++) acc[a][b][c] = 0.0f;

    // ------------------------------------------------------------------
    // GEMM2: D1[64,256] = X1[64,256] @ W2. 4 chunks of k=64 (SW128),
    // double-buffered cp.async, one sync per chunk.
    // ------------------------------------------------------------------
    for (int kc = 0; kc < 4; kc++) {
        int s = kc & 1;
        CP_WAIT0();
        __syncthreads();   // publishes X1 (kc==0) and B2(kc)
        if (kc < 3) {
            uint32_t db = smem_base + OFF_B2 + (uint32_t)(s ^ 1) * 32768u;
            const unsigned char* gw = g_w2 + (kc + 1) * 32768;
            #pragma unroll
            for (int i = 0; i < 8; i++) {
                uint32_t o = (uint32_t)(tid * 16 + i * 4096);
                CP16(db + o, gw + o);
            }
            CP_COMMIT();
        }
        mma_chunk(acc, smem_base + OFF_X1 + (uint32_t)kc * 8192u,
                  smem_base + OFF_B2 + (uint32_t)s * 32768u,
                  warp_m, warp_n, lane);
    }

    // ------------------------------------------------------------------
    // Epilogue 2 (fused GEMM3): out[m,:] = ReLU(D1[m,:]) @ W3[256,2]
    // ------------------------------------------------------------------
    {
        float p[4][2];
        #pragma unroll
        for (int r = 0; r < 4; r++) { p[r][0] = 0.f; p[r][1] = 0.f; }
        int qb = 2 * (lane & 3);
        #pragma unroll
        for (int mf = 0; mf < 2; mf++) {
            #pragma unroll
            for (int nf = 0; nf < 8; nf++) {
                #pragma unroll
                for (int i = 0; i < 4; i++) {
                    float v = acc[mf][nf][i];
                    v = v > 0.f ? v : 0.f;
                    int rsel = mf * 2 + (i >> 1);
                    int n = warp_n * 64 + nf * 8 + qb + (i & 1);
                    p[rsel][0] = fmaf(v, w3s[2 * n],     p[rsel][0]);
                    p[rsel][1] = fmaf(v, w3s[2 * n + 1], p[rsel][1]);
                }
            }
        }
        #pragma unroll
        for (int r = 0; r < 4; r++) {
            #pragma unroll
            for (int c = 0; c < 2; c++) {
                p[r][c] += __shfl_xor_sync(0xffffffffu, p[r][c], 1);
                p[r][c] += __shfl_xor_sync(0xffffffffu, p[r][c], 2);
            }
        }
        if ((lane & 3) == 0) {
            #pragma unroll
            for (int r = 0; r < 4; r++) {
                int row = warp_m * 32 + (r >> 1) * 16 + (r & 1) * 8 + (lane >> 2);
                atomicAdd(&sm_out[row * 2 + 0], p[r][0]);
                atomicAdd(&sm_out[row * 2 + 1], p[r][1]);
            }
        }
    }
    __syncthreads();
    if (tid < 128)
        out[(size_t)gbase * 2 + tid] = sm_out[tid];
}

// ============================================================================
// Launch
// ============================================================================
extern "C" void kernel_launch(void* const* d_in, const int* in_sizes, int n_in,
                              void* d_out, int out_size) {
    const float* h_nodes = (const float*)d_in[0];
    const void*  dstp    = d_in[1];
    const void*  srcp    = d_in[2];
    const float* W1      = (const float*)d_in[3];
    const float* W2      = (const float*)d_in[4];
    const float* W3      = (const float*)d_in[5];
    float*       out     = (float*)d_out;

    prep_nodes_kernel<<<12500, 256>>>(h_nodes);
    prep_weights_kernel<<<768, 256>>>(W1, W2);

    cudaFuncSetAttribute(edge_mlp_kernel,
                         cudaFuncAttributeMaxDynamicSharedMemorySize, SMEM_TOTAL);
    edge_mlp_kernel<<<NTILES, THREADS, SMEM_TOTAL>>>(dstp, srcp, W3, out);
}

// round 13
// speedup vs baseline: 3.4153x; 1.0120x over previous
#include <cuda_runtime.h>
#include <cuda_fp16.h>
#include <stdint.h>

// ============================================================================
// Problem constants
// ============================================================================
#define P_PAIRS   524288
#define NUM_NODES 100000
#define TILE_M    64
#define NTILES    (P_PAIRS / TILE_M)   // 8192
#define THREADS   256

// ---------------- Main-kernel SMEM layout (100 KB -> 2 CTAs/SM) --------------
#define OFF_IDX     0         // 128 int32
#define OFF_W3      1024      // 512 floats
#define OFF_OUT     3072      // 128 floats
#define OFF_X1      4096      // 4 tiles x [64 x 64] fp16 = 32 KB
#define OFF_B2      36864     // 2 stages x 32 KB = 64 KB
#define SMEM_TOTAL  102400

// ---------------- prep_y SMEM layout (96 KB -> 2 CTAs/SM) --------------------
#define P_OFF_A     0         // 4 tiles x 8 KB = 32 KB
#define P_OFF_B     32768     // 2 stages x 32 KB = 64 KB
#define P_SMEM      98304

// ============================================================================
// Device scratch:
//  g_ytop/g_ybot : per-node projections h@W1_top / h@W1_bot, fp16 [node][256]
//  g_w1/g_w2     : weights fp16, [N][K] SW128-swizzled 64-k-chunk tile images
// ============================================================================
__device__ __align__(16) __half g_ytop[(size_t)NUM_NODES * 256];
__device__ __align__(16) __half g_ybot[(size_t)NUM_NODES * 256];
__device__ __align__(16) unsigned char g_w1[262144];
__device__ __align__(16) unsigned char g_w2[131072];

// ============================================================================
// Helpers (plain sm_103-level PTX: ldmatrix / mma.sync / cp.async only)
// ============================================================================
__device__ __forceinline__ uint32_t smem_to_u32(const void* p) {
    uint32_t a;
    asm("{ .reg .u64 t; cvta.to.shared.u64 t, %1; cvt.u32.u64 %0, t; }"
        : "=r"(a) : "l"(p));
    return a;
}

#define SWZ128(o) ((o) ^ (((o) >> 3) & 0x70))

#define CP16(dst, src) \
    asm volatile("cp.async.cg.shared.global [%0], [%1], 16;" \
        :: "r"(dst), "l"(src))
#define CP_COMMIT() asm volatile("cp.async.commit_group;")
#define CP_WAIT0()  asm volatile("cp.async.wait_group 0;" ::: "memory")

// ldmatrix.x4: 16x16 fp16 tile from SW128 image with 128-B rows
__device__ __forceinline__ void ldsm4(uint32_t* d, uint32_t base, int r0,
                                      int ks, int lane) {
    int r = r0 + (lane & 15);
    uint32_t byte = (uint32_t)(r * 128 + ks * 32 + (lane >> 4) * 16);
    uint32_t addr = base + SWZ128(byte);
    asm volatile("ldmatrix.sync.aligned.m8n8.x4.shared.b16 {%0,%1,%2,%3}, [%4];"
        : "=r"(d[0]), "=r"(d[1]), "=r"(d[2]), "=r"(d[3]) : "r"(addr));
}

__device__ __forceinline__ void mma16816(float* c, const uint32_t* a,
                                         uint32_t b0, uint32_t b1) {
    asm volatile(
        "mma.sync.aligned.m16n8k16.row.col.f32.f16.f16.f32 "
        "{%0,%1,%2,%3}, {%4,%5,%6,%7}, {%8,%9}, {%0,%1,%2,%3};"
        : "+f"(c[0]), "+f"(c[1]), "+f"(c[2]), "+f"(c[3])
        : "r"(a[0]), "r"(a[1]), "r"(a[2]), "r"(a[3]), "r"(b0), "r"(b1));
}

__device__ __forceinline__ uint32_t pack_h2(float a, float b) {
    __half2 h = __floats2half2_rn(a, b);   // a -> low half
    return *reinterpret_cast<uint32_t*>(&h);
}

__device__ __forceinline__ uint32_t hadd_relu(uint32_t a, uint32_t b) {
    __half2 s = __hadd2(*reinterpret_cast<__half2*>(&a),
                        *reinterpret_cast<__half2*>(&b));
    __half2 z = __float2half2_rn(0.0f);
    s = __hmax2(s, z);
    return *reinterpret_cast<uint32_t*>(&s);
}

// ============================================================================
// 64-k-chunk compute. A fragments ks-double-buffered; B fragments prefetched
// at distance 2 so >=2 ldsm are in flight while the tensor pipe drains.
// ============================================================================
__device__ __forceinline__ void mma_chunk(float (&acc)[2][8][4], uint32_t aB,
                                          uint32_t bB, int warp_m, int warp_n,
                                          int lane) {
    uint32_t af[2][2][4];
    uint32_t bf[16][4];
    ldsm4(af[0][0], aB, warp_m * 32,      0, lane);
    ldsm4(af[0][1], aB, warp_m * 32 + 16, 0, lane);
    ldsm4(bf[0], bB, warp_n * 64 +  0, 0, lane);
    ldsm4(bf[1], bB, warp_n * 64 + 16, 0, lane);
    #pragma unroll
    for (int i = 0; i < 16; i++) {
        int ks = i >> 2, ng = i & 3;
        if (ng == 0 && ks < 3) {
            ldsm4(af[(ks + 1) & 1][0], aB, warp_m * 32,      ks + 1, lane);
            ldsm4(af[(ks + 1) & 1][1], aB, warp_m * 32 + 16, ks + 1, lane);
        }
        if (i < 14) {
            int j = i + 2;
            ldsm4(bf[j], bB, warp_n * 64 + (j & 3) * 16, j >> 2, lane);
        }
        const uint32_t* a0 = af[ks & 1][0];
        const uint32_t* a1 = af[ks & 1][1];
        mma16816(acc[0][ng * 2 + 0], a0, bf[i][0], bf[i][2]);
        mma16816(acc[0][ng * 2 + 1], a0, bf[i][1], bf[i][3]);
        mma16816(acc[1][ng * 2 + 0], a1, bf[i][0], bf[i][2]);
        mma16816(acc[1][ng * 2 + 1], a1, bf[i][1], bf[i][3]);
    }
}

// ============================================================================
// Prologue 1: W1/W2 ([K][N] row-major) -> fp16 [N][K] SW128 swizzled images.
// g_w1 chunk c holds B[n][k'] = W1[c*64+k'][n]; chunks 0-3 = W1_top (k<256),
// chunks 4-7 = W1_bot.
// ============================================================================
__global__ void prep_weights_kernel(const float* __restrict__ W1,
                                    const float* __restrict__ W2) {
    int t = blockIdx.x * blockDim.x + threadIdx.x;
    if (t < 512 * 256) {
        int k = t >> 8, n = t & 255;
        __half h = __float2half_rn(W1[t]);
        uint32_t off = (uint32_t)(n * 128 + (k & 63) * 2);
        uint32_t a = SWZ128(off) + (uint32_t)(k >> 6) * 32768u;
        *(unsigned short*)(g_w1 + a) = *(unsigned short*)&h;
    } else {
        int t2 = t - 512 * 256;
        if (t2 < 256 * 256) {
            int k = t2 >> 8, n = t2 & 255;
            __half h = __float2half_rn(W2[t2]);
            uint32_t off = (uint32_t)(n * 128 + (k & 63) * 2);
            uint32_t a = SWZ128(off) + (uint32_t)(k >> 6) * 32768u;
            *(unsigned short*)(g_w2 + a) = *(unsigned short*)&h;
        }
    }
}

// ============================================================================
// Prologue 2: per-node projections. CTA = 64 node rows; A (h rows, fp16) held
// in smem across both passes; B double-buffered over g_w1 chunks 0-7.
// Pass 0 (chunks 0-3) -> Y_top, pass 1 (chunks 4-7) -> Y_bot. No relu.
// ============================================================================
__global__ void __launch_bounds__(THREADS, 2)
prep_y_kernel(const float* __restrict__ h) {
    extern __shared__ unsigned char smem[];
    uint32_t smem_base = smem_to_u32(smem);
    int tid  = threadIdx.x;
    int lane = tid & 31;
    int wid  = tid >> 5;
    int warp_m = wid & 1;
    int warp_n = wid >> 1;
    int row0 = blockIdx.x * 64;

    // ---- A fill: 64 rows x 256 fp32 -> fp16, 4 SW128 tiles of [64 x 64] ----
    {
        int m_row = tid >> 2, part = tid & 3;
        int row = row0 + m_row;
        if (row >= NUM_NODES) row = NUM_NODES - 1;   // clamp (store guarded)
        const float4* rp = (const float4*)(h + (size_t)row * 256);
        #pragma unroll
        for (int kc = 0; kc < 4; kc++) {
            float4 v0 = rp[kc * 16 + part * 4 + 0];
            float4 v1 = rp[kc * 16 + part * 4 + 1];
            float4 v2 = rp[kc * 16 + part * 4 + 2];
            float4 v3 = rp[kc * 16 + part * 4 + 3];
            unsigned char* ap = smem + P_OFF_A + kc * 8192;
            uint32_t sw0 = SWZ128((uint32_t)(m_row * 128 + part * 32));
            uint32_t sw1 = SWZ128((uint32_t)(m_row * 128 + part * 32 + 16));
            uint4 s0, s1;
            s0.x = pack_h2(v0.x, v0.y); s0.y = pack_h2(v0.z, v0.w);
            s0.z = pack_h2(v1.x, v1.y); s0.w = pack_h2(v1.z, v1.w);
            s1.x = pack_h2(v2.x, v2.y); s1.y = pack_h2(v2.z, v2.w);
            s1.z = pack_h2(v3.x, v3.y); s1.w = pack_h2(v3.z, v3.w);
            *(uint4*)(ap + sw0) = s0;
            *(uint4*)(ap + sw1) = s1;
        }
    }
    // B(0)
    {
        uint32_t db = smem_base + P_OFF_B;
        #pragma unroll
        for (int i = 0; i < 8; i++) {
            uint32_t o = (uint32_t)(tid * 16 + i * 4096);
            CP16(db + o, g_w1 + o);
        }
        CP_COMMIT();
    }

    float acc[2][8][4];
    #pragma unroll
    for (int a = 0; a < 2; a++)
        #pragma unroll
        for (int b = 0; b < 8; b++)
            #pragma unroll
            for (int c = 0; c < 4; c++) acc[a][b][c] = 0.0f;

    for (int idx = 0; idx < 8; idx++) {
        int s = idx & 1;
        CP_WAIT0();
        __syncthreads();   // publishes A (idx==0) and B(idx)
        if (idx < 7) {
            uint32_t db = smem_base + P_OFF_B + (uint32_t)(s ^ 1) * 32768u;
            const unsigned char* gw = g_w1 + (idx + 1) * 32768;
            #pragma unroll
            for (int i = 0; i < 8; i++) {
                uint32_t o = (uint32_t)(tid * 16 + i * 4096);
                CP16(db + o, gw + o);
            }
            CP_COMMIT();
        }
        mma_chunk(acc, smem_base + P_OFF_A + (uint32_t)(idx & 3) * 8192u,
                  smem_base + P_OFF_B + (uint32_t)s * 32768u,
                  warp_m, warp_n, lane);
        if ((idx & 3) == 3) {
            // store this half's Y (fp32 acc -> fp16), then reset acc
            __half* Y = (idx < 4) ? g_ytop : g_ybot;
            int qb = 2 * (lane & 3);
            #pragma unroll
            for (int mf = 0; mf < 2; mf++) {
                #pragma unroll
                for (int nf = 0; nf < 8; nf++) {
                    #pragma unroll
                    for (int half = 0; half < 2; half++) {
                        int row = row0 + warp_m * 32 + mf * 16 + half * 8 +
                                  (lane >> 2);
                        int col = warp_n * 64 + nf * 8 + qb;
                        if (row < NUM_NODES) {
                            *(uint32_t*)(Y + (size_t)row * 256 + col) =
                                pack_h2(acc[mf][nf][half * 2 + 0],
                                        acc[mf][nf][half * 2 + 1]);
                        }
                        acc[mf][nf][half * 2 + 0] = 0.0f;
                        acc[mf][nf][half * 2 + 1] = 0.0f;
                    }
                }
            }
        }
    }
}

// ============================================================================
// Main fused kernel. CTA = 64 pairs, 8 warps, 2 CTAs/SM.
// X1 = relu(Y_top[dst] + Y_bot[src]) via gather + fp16 add; then GEMM2 + W3.
// ============================================================================
__global__ void __launch_bounds__(THREADS, 2)
edge_mlp_kernel(const void*  __restrict__ dstp,
                const void*  __restrict__ srcp,
                const float* __restrict__ W3,
                float*       __restrict__ out) {
    extern __shared__ unsigned char smem[];
    uint32_t smem_base = smem_to_u32(smem);
    int tid  = threadIdx.x;
    int lane = tid & 31;
    int wid  = tid >> 5;
    int warp_m = wid & 1;    // 0..1 -> 32 M-rows each
    int warp_n = wid >> 1;   // 0..3 -> 64 N-cols each

    int gbase = blockIdx.x * TILE_M;

    // B2 chunk 0: no dependencies, issue immediately
    {
        uint32_t db = smem_base + OFF_B2;
        #pragma unroll
        for (int i = 0; i < 8; i++) {
            uint32_t o = (uint32_t)(tid * 16 + i * 4096);
            CP16(db + o, g_w2 + o);
        }
        CP_COMMIT();
    }

    // ---- index-dtype detection on the first 64 entries (in-bounds for both
    // dtypes; int64 buffers have all odd 32-bit words zero) ----
    int odd = 0;
    if (tid < 64)       odd = ((const int*)dstp)[2 * tid + 1];
    else if (tid < 128) odd = ((const int*)srcp)[2 * (tid - 64) + 1];
    bool i64 = (__syncthreads_or(odd != 0) == 0);

    // ---- indices, W3, zero out-accum ----
    int* sm_idx = (int*)(smem + OFF_IDX);
    if (tid < 64) {
        sm_idx[tid] = i64 ? (int)((const long long*)dstp)[gbase + tid]
                          : ((const int*)dstp)[gbase + tid];
    } else if (tid < 128) {
        int t = tid - 64;
        sm_idx[64 + t] = i64 ? (int)((const long long*)srcp)[gbase + t]
                             : ((const int*)srcp)[gbase + t];
    }
    float* w3s = (float*)(smem + OFF_W3);
    w3s[tid] = W3[tid];
    w3s[tid + 256] = W3[tid + 256];
    float* sm_out = (float*)(smem + OFF_OUT);
    if (tid < 128) sm_out[tid] = 0.0f;
    __syncthreads();

    // ---- gather + add + relu -> X1 (4 SW128 tiles of [64 x 64]) ----
    {
        int m_row = tid >> 2, part = tid & 3;
        const uint4* yt = (const uint4*)(g_ytop +
                          (size_t)sm_idx[m_row] * 256) + part * 8;
        const uint4* yb = (const uint4*)(g_ybot +
                          (size_t)sm_idx[64 + m_row] * 256) + part * 8;
        unsigned char* x1 = smem + OFF_X1 + part * 8192;
        #pragma unroll
        for (int j = 0; j < 8; j++) {
            uint4 a = yt[j], b = yb[j], c;
            c.x = hadd_relu(a.x, b.x);
            c.y = hadd_relu(a.y, b.y);
            c.z = hadd_relu(a.z, b.z);
            c.w = hadd_relu(a.w, b.w);
            *(uint4*)(x1 + SWZ128((uint32_t)(m_row * 128 + j * 16))) = c;
        }
    }

    float acc[2][8][4];
    #pragma unroll
    for (int a = 0; a < 2; a++)
        #pragma unroll
        for (int b = 0; b < 8; b++)
            #pragma unroll
            for (int c = 0; c < 4; c++) acc[a][b][c] = 0.0f;

    // ------------------------------------------------------------------
    // GEMM2: D1[64,256] = X1[64,256] @ W2. 4 chunks of k=64 (SW128),
    // double-buffered cp.async, one sync per chunk.
    // ------------------------------------------------------------------
    for (int kc = 0; kc < 4; kc++) {
        int s = kc & 1;
        CP_WAIT0();
        __syncthreads();   // publishes X1 (kc==0) and B2(kc)
        if (kc < 3) {
            uint32_t db = smem_base + OFF_B2 + (uint32_t)(s ^ 1) * 32768u;
            const unsigned char* gw = g_w2 + (kc + 1) * 32768;
            #pragma unroll
            for (int i = 0; i < 8; i++) {
                uint32_t o = (uint32_t)(tid * 16 + i * 4096);
                CP16(db + o, gw + o);
            }
            CP_COMMIT();
        }
        mma_chunk(acc, smem_base + OFF_X1 + (uint32_t)kc * 8192u,
                  smem_base + OFF_B2 + (uint32_t)s * 32768u,
                  warp_m, warp_n, lane);
    }

    // ------------------------------------------------------------------
    // Epilogue (fused GEMM3): out[m,:] = ReLU(D1[m,:]) @ W3[256,2]
    // ------------------------------------------------------------------
    {
        float p[4][2];
        #pragma unroll
        for (int r = 0; r < 4; r++) { p[r][0] = 0.f; p[r][1] = 0.f; }
        int qb = 2 * (lane & 3);
        #pragma unroll
        for (int mf = 0; mf < 2; mf++) {
            #pragma unroll
            for (int nf = 0; nf < 8; nf++) {
                #pragma unroll
                for (int i = 0; i < 4; i++) {
                    float v = acc[mf][nf][i];
                    v = v > 0.f ? v : 0.f;
                    int rsel = mf * 2 + (i >> 1);
                    int n = warp_n * 64 + nf * 8 + qb + (i & 1);
                    p[rsel][0] = fmaf(v, w3s[2 * n],     p[rsel][0]);
                    p[rsel][1] = fmaf(v, w3s[2 * n + 1], p[rsel][1]);
                }
            }
        }
        #pragma unroll
        for (int r = 0; r < 4; r++) {
            #pragma unroll
            for (int c = 0; c < 2; c++) {
                p[r][c] += __shfl_xor_sync(0xffffffffu, p[r][c], 1);
                p[r][c] += __shfl_xor_sync(0xffffffffu, p[r][c], 2);
            }
        }
        if ((lane & 3) == 0) {
            #pragma unroll
            for (int r = 0; r < 4; r++) {
                int row = warp_m * 32 + (r >> 1) * 16 + (r & 1) * 8 + (lane >> 2);
                atomicAdd(&sm_out[row * 2 + 0], p[r][0]);
                atomicAdd(&sm_out[row * 2 + 1], p[r][1]);
            }
        }
    }
    __syncthreads();
    if (tid < 128)
        out[(size_t)gbase * 2 + tid] = sm_out[tid];
}

// ============================================================================
// Launch
// ============================================================================
extern "C" void kernel_launch(void* const* d_in, const int* in_sizes, int n_in,
                              void* d_out, int out_size) {
    const float* h_nodes = (const float*)d_in[0];
    const void*  dstp    = d_in[1];
    const void*  srcp    = d_in[2];
    const float* W1      = (const float*)d_in[3];
    const float* W2      = (const float*)d_in[4];
    const float* W3      = (const float*)d_in[5];
    float*       out     = (float*)d_out;

    prep_weights_kernel<<<768, 256>>>(W1, W2);

    cudaFuncSetAttribute(prep_y_kernel,
                         cudaFuncAttributeMaxDynamicSharedMemorySize, P_SMEM);
    prep_y_kernel<<<(NUM_NODES + 63) / 64, THREADS, P_SMEM>>>(h_nodes);

    cudaFuncSetAttribute(edge_mlp_kernel,
                         cudaFuncAttributeMaxDynamicSharedMemorySize, SMEM_TOTAL);
    edge_mlp_kernel<<<NTILES, THREADS, SMEM_TOTAL>>>(dstp, srcp, W3, out);
}